// round 4
// baseline (speedup 1.0000x reference)
#include <cuda_runtime.h>
#include <math.h>

#define NROWS 32768
#define DIM   256
#define KCODE 4096

// ---------------- scratch ------------------------------------------------------
__device__ float  g_wnorm[KCODE];
__device__ float  g_xnorm[NROWS];
__device__ int    g_idx[NROWS];
__device__ int    g_counts[KCODE];
__device__ double g_part[NROWS / 8];

// ---------------- K1: zero counts ----------------------------------------------
__global__ void zero_counts_kernel() {
    int i = blockIdx.x * blockDim.x + threadIdx.x;
    if (i < KCODE) g_counts[i] = 0;
}

// ---------------- K2: XLA:CPU-emulated sum of squares --------------------------
// Emulates XLA CPU vectorized reduce on NEON (VF=4):
//   acc[l] = sum_i fmul(x[4i+l], x[4i+l])  (i sequential, separate rn mul/add)
//   result = (acc0+acc2) + (acc1+acc3)     (halving-shuffle combine)
// 4 threads per row; lane l = tid & 3.
__global__ void xla_norm_kernel(const float* __restrict__ A, float* __restrict__ out,
                                int nrows) {
    int gtid = blockIdx.x * blockDim.x + threadIdx.x;
    int row = gtid >> 2;
    int l = gtid & 3;
    if (row >= nrows) return;
    const float* r = A + (size_t)row * DIM;
    float a = 0.f;
    #pragma unroll 8
    for (int i = 0; i < DIM / 4; i++) {
        float v = __ldg(&r[4 * i + l]);
        a = __fadd_rn(a, __fmul_rn(v, v));
    }
    float b = __shfl_xor_sync(0xffffffffu, a, 2);
    float t = __fadd_rn(a, b);                       // lane0: a0+a2, lane1: a1+a3
    float c = __shfl_xor_sync(0xffffffffu, t, 1);
    float s = __fadd_rn(t, c);                       // (a0+a2)+(a1+a3)
    if (l == 0) out[row] = s;
}

// ---------------- K3: fused distance GEMM + argmin (grid-quantized compare) ----
#define TM  64
#define TKC 64
#define DS  32

__global__ __launch_bounds__(256)
void dist_argmin_kernel(const float* __restrict__ X, const float* __restrict__ W) {
    __shared__ float sX[DS][TM];
    __shared__ float sW[DS][TKC];
    __shared__ float rv[16][TM];
    __shared__ int   ri[16][TM];

    int tid = threadIdx.x;
    int tx = tid & 15;    // code dim
    int ty = tid >> 4;    // row dim
    int rowBase = blockIdx.x * TM;

    float xn[4];
    #pragma unroll
    for (int r = 0; r < 4; r++) xn[r] = g_xnorm[rowBase + ty * 4 + r];

    float minv[4];
    int   mini[4];
    #pragma unroll
    for (int r = 0; r < 4; r++) { minv[r] = 3.4e38f; mini[r] = 0; }

    for (int k0 = 0; k0 < KCODE; k0 += TKC) {
        float acc[4][4];
        #pragma unroll
        for (int r = 0; r < 4; r++)
            #pragma unroll
            for (int c = 0; c < 4; c++) acc[r][c] = 0.f;

        for (int d0 = 0; d0 < DIM; d0 += DS) {
            __syncthreads();
            #pragma unroll
            for (int l = 0; l < 2; l++) {
                int idx = l * 256 + tid;
                int r  = idx & 63;
                int c4 = idx >> 6;
                float4 v = *(const float4*)&X[(size_t)(rowBase + r) * DIM + d0 + c4 * 4];
                sX[c4 * 4 + 0][r] = v.x;
                sX[c4 * 4 + 1][r] = v.y;
                sX[c4 * 4 + 2][r] = v.z;
                sX[c4 * 4 + 3][r] = v.w;
                float4 w = *(const float4*)&W[(size_t)(k0 + r) * DIM + d0 + c4 * 4];
                sW[c4 * 4 + 0][r] = w.x;
                sW[c4 * 4 + 1][r] = w.y;
                sW[c4 * 4 + 2][r] = w.z;
                sW[c4 * 4 + 3][r] = w.w;
            }
            __syncthreads();
            #pragma unroll
            for (int dd = 0; dd < DS; dd++) {
                float4 a = *(const float4*)&sX[dd][ty * 4];
                float4 b = *(const float4*)&sW[dd][tx * 4];
                acc[0][0] += a.x * b.x; acc[0][1] += a.x * b.y; acc[0][2] += a.x * b.z; acc[0][3] += a.x * b.w;
                acc[1][0] += a.y * b.x; acc[1][1] += a.y * b.y; acc[1][2] += a.y * b.z; acc[1][3] += a.y * b.w;
                acc[2][0] += a.z * b.x; acc[2][1] += a.z * b.y; acc[2][2] += a.z * b.z; acc[2][3] += a.z * b.w;
                acc[3][0] += a.w * b.x; acc[3][1] += a.w * b.y; acc[3][2] += a.w * b.z; acc[3][3] += a.w * b.w;
            }
        }
        // reference-faithful compare value:
        //   dist = fp32( fp32(xnorm + wnorm) - 2*dot )  -> quantized at ulp(~256)
        // strict < keeps lowest index on grid ties (jnp.argmin semantics)
        #pragma unroll
        for (int c = 0; c < 4; c++) {
            int k = k0 + tx * 4 + c;
            float wnv = g_wnorm[k];
            #pragma unroll
            for (int r = 0; r < 4; r++) {
                float T = __fadd_rn(xn[r], wnv);
                float dist = __fadd_rn(T, __fmul_rn(-2.0f, acc[r][c]));
                if (dist < minv[r]) { minv[r] = dist; mini[r] = k; }
            }
        }
    }

    __syncthreads();
    #pragma unroll
    for (int r = 0; r < 4; r++) {
        rv[tx][ty * 4 + r] = minv[r];
        ri[tx][ty * 4 + r] = mini[r];
    }
    __syncthreads();
    if (tid < TM) {
        float bv = rv[0][tid];
        int   bi = ri[0][tid];
        #pragma unroll
        for (int t = 1; t < 16; t++) {
            float v = rv[t][tid];
            int   i = ri[t][tid];
            if (v < bv || (v == bv && i < bi)) { bv = v; bi = i; }
        }
        g_idx[rowBase + tid] = bi;
    }
}

// ---------------- K4: gather / quantized_st / loss partials / histogram --------
__global__ __launch_bounds__(256)
void quantize_kernel(const float* __restrict__ X, const float* __restrict__ W,
                     float* q_out) {
    __shared__ double sh[8];
    int warp = threadIdx.x >> 5;
    int lane = threadIdx.x & 31;
    int row = blockIdx.x * 8 + warp;
    int idx = g_idx[row];
    if (lane == 0) atomicAdd(&g_counts[idx], 1);

    const float* xr = X + (size_t)row * DIM;
    const float* wr = W + (size_t)idx * DIM;
    double s = 0.0;
    #pragma unroll
    for (int j = 0; j < 2; j++) {
        int d = lane * 8 + j * 4;
        float4 xv = *(const float4*)&xr[d];
        float4 wv = *(const float4*)&wr[d];
        float t0 = wv.x - xv.x, t1 = wv.y - xv.y, t2 = wv.z - xv.z, t3 = wv.w - xv.w;
        if (q_out) {
            float* o = q_out + (size_t)row * DIM + d;
            o[0] = xv.x + t0; o[1] = xv.y + t1; o[2] = xv.z + t2; o[3] = xv.w + t3;
        }
        s += (double)t0 * t0 + (double)t1 * t1 + (double)t2 * t2 + (double)t3 * t3;
    }
    #pragma unroll
    for (int o = 16; o > 0; o >>= 1) s += __shfl_down_sync(0xffffffffu, s, o);
    if (lane == 0) sh[warp] = s;
    __syncthreads();
    if (threadIdx.x == 0) {
        double t = 0.0;
        #pragma unroll
        for (int w = 0; w < 8; w++) t += sh[w];
        g_part[blockIdx.x] = t;
    }
}

// ---------------- K5: finalize loss + perplexity -------------------------------
__global__ void finalize_kernel(float* loss_out, float* perp_out) {
    __shared__ double sh[1024];
    int tid = threadIdx.x;
    double s = 0.0;
    for (int i = tid; i < NROWS / 8; i += 1024) s += g_part[i];
    sh[tid] = s;
    __syncthreads();
    for (int o = 512; o > 0; o >>= 1) {
        if (tid < o) sh[tid] += sh[tid + o];
        __syncthreads();
    }
    double total = sh[0];
    __syncthreads();

    double e = 0.0;
    for (int i = tid; i < KCODE; i += 1024) {
        double p = (double)g_counts[i] / (double)NROWS;
        e += p * log(p + 1e-10);
    }
    sh[tid] = e;
    __syncthreads();
    for (int o = 512; o > 0; o >>= 1) {
        if (tid < o) sh[tid] += sh[tid + o];
        __syncthreads();
    }
    if (tid == 0) {
        double mse = total / ((double)NROWS * (double)DIM);
        if (loss_out) *loss_out = (float)(1.25 * mse);
        if (perp_out) *perp_out = (float)exp(-sh[0]);
    }
}

// ---------------- K6: zero encodings -------------------------------------------
__global__ void zero_enc_kernel(unsigned long long* enc, long long n8) {
    long long i = (long long)blockIdx.x * blockDim.x + threadIdx.x;
    long long stride = (long long)gridDim.x * blockDim.x;
    for (; i < n8; i += stride) enc[i] = 0ull;
}

// ---------------- K7: scatter one-hot ------------------------------------------
__global__ void scatter_kernel(float* enc) {
    int row = blockIdx.x * blockDim.x + threadIdx.x;
    int stride = gridDim.x * blockDim.x;
    for (; row < NROWS; row += stride)
        enc[(size_t)row * KCODE + g_idx[row]] = 1.0f;
}

// ---------------- launch -------------------------------------------------------
extern "C" void kernel_launch(void* const* d_in, const int* in_sizes, int n_in,
                              void* d_out, int out_size) {
    const float* X = (const float*)d_in[0];
    const float* W = (const float*)d_in[1];
    if (n_in >= 2 && in_sizes[0] == KCODE * DIM && in_sizes[1] == NROWS * DIM) {
        X = (const float*)d_in[1];
        W = (const float*)d_in[0];
    }

    float* out = (float*)d_out;
    const long long FULL = 2LL + (long long)NROWS * DIM + (long long)NROWS * KCODE;

    float* loss_p = nullptr;
    float* q_p    = nullptr;
    float* perp_p = nullptr;
    float* enc_p  = nullptr;

    if ((long long)out_size == FULL) {
        loss_p = out;
        q_p    = out + 1;
        perp_p = out + 1 + (long long)NROWS * DIM;
        enc_p  = out + 2 + (long long)NROWS * DIM;
    } else if (out_size == NROWS * DIM) {
        q_p = out;
    } else if (out_size == NROWS * KCODE) {
        enc_p = out;
    } else if (out_size == 2) {
        loss_p = out;
        perp_p = out + 1;
    } else if (out_size == 1) {
        loss_p = out;
    } else {
        loss_p = out;
        if (out_size > 1 + NROWS * DIM) q_p = out + 1;
    }

    float* xn; cudaGetSymbolAddress((void**)&xn, g_xnorm);
    float* wn; cudaGetSymbolAddress((void**)&wn, g_wnorm);

    zero_counts_kernel<<<16, 256>>>();
    xla_norm_kernel<<<(NROWS * 4) / 256, 256>>>(X, xn, NROWS);
    xla_norm_kernel<<<(KCODE * 4) / 256, 256>>>(W, wn, KCODE);
    dist_argmin_kernel<<<NROWS / TM, 256>>>(X, W);
    quantize_kernel<<<NROWS / 8, 256>>>(X, W, q_p);
    finalize_kernel<<<1, 1024>>>(loss_p, perp_p);
    if (enc_p) {
        long long n8 = (long long)NROWS * KCODE / 2;
        zero_enc_kernel<<<2048, 256>>>((unsigned long long*)enc_p, n8);
        scatter_kernel<<<128, 256>>>(enc_p);
    }
}

// round 5
// speedup vs baseline: 1.3249x; 1.3249x over previous
#include <cuda_runtime.h>
#include <math.h>

#define NROWS 32768
#define DIM   256
#define KCODE 4096

// ---------------- scratch ------------------------------------------------------
__device__ float  g_wnorm[KCODE];
__device__ float  g_xnorm[NROWS];
__device__ int    g_idx[NROWS];
__device__ int    g_counts[KCODE];
__device__ double g_part[NROWS / 8];

// ---------------- K1: zero counts ----------------------------------------------
__global__ void zero_counts_kernel() {
    int i = blockIdx.x * blockDim.x + threadIdx.x;
    if (i < KCODE) g_counts[i] = 0;
}

// ---------------- K2: XLA:CPU-emulated sum of squares (DO NOT TOUCH) -----------
// Emulates XLA CPU vectorized reduce on NEON (VF=4). This sets the rounding-cell
// offset of the compared distances; bit-exactness here is what makes argmin ties
// resolve identically to the reference.
__global__ void xla_norm_kernel(const float* __restrict__ A, float* __restrict__ out,
                                int nrows) {
    int gtid = blockIdx.x * blockDim.x + threadIdx.x;
    int row = gtid >> 2;
    int l = gtid & 3;
    if (row >= nrows) return;
    const float* r = A + (size_t)row * DIM;
    float a = 0.f;
    #pragma unroll 8
    for (int i = 0; i < DIM / 4; i++) {
        float v = __ldg(&r[4 * i + l]);
        a = __fadd_rn(a, __fmul_rn(v, v));
    }
    float b = __shfl_xor_sync(0xffffffffu, a, 2);
    float t = __fadd_rn(a, b);
    float c = __shfl_xor_sync(0xffffffffu, t, 1);
    float s = __fadd_rn(t, c);
    if (l == 0) out[row] = s;
}

// ---------------- K3: fused distance GEMM + argmin, FFMA2 (f32x2) path ---------
// Block tile 128 rows x 128 codes, thread tile 8x8, 256 threads (16x16).
// X tile stored lane-DUPLICATED in smem ({x,x} pairs) so ld.shared.v2.b64 yields
// ready-packed broadcast operands for fma.rn.f32x2. W tile d-major: adjacent
// codes are contiguous -> natural f32x2 pairs.
#define TMR 128
#define TKK 128
#define DS  16

__global__ __launch_bounds__(256)
void dist_argmin_kernel(const float* __restrict__ X, const float* __restrict__ W) {
    __shared__ float sXd[2][DS][2 * TMR];   // 32 KB (rows duplicated)
    __shared__ float sWt[2][DS][TKK];       // 16 KB
    __shared__ float rv[16][TMR];           // 8 KB
    __shared__ int   ri[16][TMR];           // 8 KB

    const int tid  = threadIdx.x;
    const int tx   = tid & 15;     // code dim (16)
    const int ty   = tid >> 4;     // row dim (16)
    const int rowBase = blockIdx.x * TMR;
    const int lrow  = tid >> 1;    // 0..127 staging row/code
    const int lhalf = tid & 1;     // 0/1 staging d-half

    unsigned sx_base = (unsigned)__cvta_generic_to_shared(&sXd[0][0][0]);
    unsigned sw_base = (unsigned)__cvta_generic_to_shared(&sWt[0][0][0]);

    const float* Xrow = X + (size_t)(rowBase + lrow) * DIM + lhalf * 8;

    float minv[8];
    int   mini[8];
    #pragma unroll
    for (int r = 0; r < 8; r++) { minv[r] = 3.4e38f; mini[r] = 0; }

    for (int k0 = 0; k0 < KCODE; k0 += TKK) {
        unsigned long long acc[8][4];
        #pragma unroll
        for (int r = 0; r < 8; r++)
            #pragma unroll
            for (int j = 0; j < 4; j++) acc[r][j] = 0ull;

        const float* Wrow = W + (size_t)(k0 + lrow) * DIM + lhalf * 8;

        float4 xr0 = *(const float4*)(Xrow + 0);
        float4 xr1 = *(const float4*)(Xrow + 4);
        float4 wr0 = *(const float4*)(Wrow + 0);
        float4 wr1 = *(const float4*)(Wrow + 4);

        int buf = 0;
        for (int s = 0; s < DIM / DS; s++) {
            // ---- store stage into buf ----
            {
                int dB = lhalf * 8;
                *(float2*)&sXd[buf][dB + 0][2 * lrow] = make_float2(xr0.x, xr0.x);
                *(float2*)&sXd[buf][dB + 1][2 * lrow] = make_float2(xr0.y, xr0.y);
                *(float2*)&sXd[buf][dB + 2][2 * lrow] = make_float2(xr0.z, xr0.z);
                *(float2*)&sXd[buf][dB + 3][2 * lrow] = make_float2(xr0.w, xr0.w);
                *(float2*)&sXd[buf][dB + 4][2 * lrow] = make_float2(xr1.x, xr1.x);
                *(float2*)&sXd[buf][dB + 5][2 * lrow] = make_float2(xr1.y, xr1.y);
                *(float2*)&sXd[buf][dB + 6][2 * lrow] = make_float2(xr1.z, xr1.z);
                *(float2*)&sXd[buf][dB + 7][2 * lrow] = make_float2(xr1.w, xr1.w);
                sWt[buf][dB + 0][lrow] = wr0.x;
                sWt[buf][dB + 1][lrow] = wr0.y;
                sWt[buf][dB + 2][lrow] = wr0.z;
                sWt[buf][dB + 3][lrow] = wr0.w;
                sWt[buf][dB + 4][lrow] = wr1.x;
                sWt[buf][dB + 5][lrow] = wr1.y;
                sWt[buf][dB + 6][lrow] = wr1.z;
                sWt[buf][dB + 7][lrow] = wr1.w;
            }
            __syncthreads();
            // ---- prefetch next stage ----
            if (s + 1 < DIM / DS) {
                int d0 = (s + 1) * DS;
                xr0 = *(const float4*)(Xrow + d0);
                xr1 = *(const float4*)(Xrow + d0 + 4);
                wr0 = *(const float4*)(Wrow + d0);
                wr1 = *(const float4*)(Wrow + d0 + 4);
            }
            // ---- compute on buf ----
            #pragma unroll
            for (int dd = 0; dd < DS; dd++) {
                unsigned long long a2[8], b2[4];
                unsigned abase = sx_base + (unsigned)(((buf * DS + dd) * 2 * TMR + ty * 16) * 4);
                unsigned bbase = sw_base + (unsigned)(((buf * DS + dd) * TKK + tx * 8) * 4);
                asm volatile("ld.shared.v2.b64 {%0,%1},[%2];"
                             : "=l"(a2[0]), "=l"(a2[1]) : "r"(abase));
                asm volatile("ld.shared.v2.b64 {%0,%1},[%2];"
                             : "=l"(a2[2]), "=l"(a2[3]) : "r"(abase + 16));
                asm volatile("ld.shared.v2.b64 {%0,%1},[%2];"
                             : "=l"(a2[4]), "=l"(a2[5]) : "r"(abase + 32));
                asm volatile("ld.shared.v2.b64 {%0,%1},[%2];"
                             : "=l"(a2[6]), "=l"(a2[7]) : "r"(abase + 48));
                asm volatile("ld.shared.v2.b64 {%0,%1},[%2];"
                             : "=l"(b2[0]), "=l"(b2[1]) : "r"(bbase));
                asm volatile("ld.shared.v2.b64 {%0,%1},[%2];"
                             : "=l"(b2[2]), "=l"(b2[3]) : "r"(bbase + 16));
                #pragma unroll
                for (int r = 0; r < 8; r++) {
                    #pragma unroll
                    for (int j = 0; j < 4; j++) {
                        asm("fma.rn.f32x2 %0, %1, %2, %0;"
                            : "+l"(acc[r][j]) : "l"(a2[r]), "l"(b2[j]));
                    }
                }
            }
            __syncthreads();
            buf ^= 1;
        }

        // ---- fold into running argmin (ascending k; strict < keeps lowest idx) --
        #pragma unroll
        for (int r = 0; r < 8; r++) {
            float xnv = g_xnorm[rowBase + ty * 8 + r];
            #pragma unroll
            for (int j = 0; j < 4; j++) {
                float lo, hi;
                asm("mov.b64 {%0,%1}, %2;" : "=f"(lo), "=f"(hi) : "l"(acc[r][j]));
                int k = k0 + tx * 8 + 2 * j;
                float wnv = g_wnorm[k];
                float T = __fadd_rn(xnv, wnv);
                float dist = __fadd_rn(T, __fmul_rn(-2.0f, lo));
                if (dist < minv[r]) { minv[r] = dist; mini[r] = k; }
                wnv = g_wnorm[k + 1];
                T = __fadd_rn(xnv, wnv);
                dist = __fadd_rn(T, __fmul_rn(-2.0f, hi));
                if (dist < minv[r]) { minv[r] = dist; mini[r] = k + 1; }
            }
        }
    }

    __syncthreads();
    #pragma unroll
    for (int r = 0; r < 8; r++) {
        rv[tx][ty * 8 + r] = minv[r];
        ri[tx][ty * 8 + r] = mini[r];
    }
    __syncthreads();
    if (tid < TMR) {
        float bv = rv[0][tid];
        int   bi = ri[0][tid];
        #pragma unroll
        for (int t = 1; t < 16; t++) {
            float v = rv[t][tid];
            int   i = ri[t][tid];
            if (v < bv || (v == bv && i < bi)) { bv = v; bi = i; }
        }
        g_idx[rowBase + tid] = bi;
    }
}

// ---------------- K4: gather / quantized_st / loss partials / histogram --------
__global__ __launch_bounds__(256)
void quantize_kernel(const float* __restrict__ X, const float* __restrict__ W,
                     float* q_out) {
    __shared__ double sh[8];
    int warp = threadIdx.x >> 5;
    int lane = threadIdx.x & 31;
    int row = blockIdx.x * 8 + warp;
    int idx = g_idx[row];
    if (lane == 0) atomicAdd(&g_counts[idx], 1);

    const float* xr = X + (size_t)row * DIM;
    const float* wr = W + (size_t)idx * DIM;
    double s = 0.0;
    #pragma unroll
    for (int j = 0; j < 2; j++) {
        int d = lane * 8 + j * 4;
        float4 xv = *(const float4*)&xr[d];
        float4 wv = *(const float4*)&wr[d];
        float t0 = wv.x - xv.x, t1 = wv.y - xv.y, t2 = wv.z - xv.z, t3 = wv.w - xv.w;
        if (q_out) {
            float* o = q_out + (size_t)row * DIM + d;
            o[0] = xv.x + t0; o[1] = xv.y + t1; o[2] = xv.z + t2; o[3] = xv.w + t3;
        }
        s += (double)t0 * t0 + (double)t1 * t1 + (double)t2 * t2 + (double)t3 * t3;
    }
    #pragma unroll
    for (int o = 16; o > 0; o >>= 1) s += __shfl_down_sync(0xffffffffu, s, o);
    if (lane == 0) sh[warp] = s;
    __syncthreads();
    if (threadIdx.x == 0) {
        double t = 0.0;
        #pragma unroll
        for (int w = 0; w < 8; w++) t += sh[w];
        g_part[blockIdx.x] = t;
    }
}

// ---------------- K5: finalize loss + perplexity -------------------------------
__global__ void finalize_kernel(float* loss_out, float* perp_out) {
    __shared__ double sh[1024];
    int tid = threadIdx.x;
    double s = 0.0;
    for (int i = tid; i < NROWS / 8; i += 1024) s += g_part[i];
    sh[tid] = s;
    __syncthreads();
    for (int o = 512; o > 0; o >>= 1) {
        if (tid < o) sh[tid] += sh[tid + o];
        __syncthreads();
    }
    double total = sh[0];
    __syncthreads();

    double e = 0.0;
    for (int i = tid; i < KCODE; i += 1024) {
        double p = (double)g_counts[i] / (double)NROWS;
        e += p * log(p + 1e-10);
    }
    sh[tid] = e;
    __syncthreads();
    for (int o = 512; o > 0; o >>= 1) {
        if (tid < o) sh[tid] += sh[tid + o];
        __syncthreads();
    }
    if (tid == 0) {
        double mse = total / ((double)NROWS * (double)DIM);
        if (loss_out) *loss_out = (float)(1.25 * mse);
        if (perp_out) *perp_out = (float)exp(-sh[0]);
    }
}

// ---------------- K6: zero encodings -------------------------------------------
__global__ void zero_enc_kernel(unsigned long long* enc, long long n8) {
    long long i = (long long)blockIdx.x * blockDim.x + threadIdx.x;
    long long stride = (long long)gridDim.x * blockDim.x;
    for (; i < n8; i += stride) enc[i] = 0ull;
}

// ---------------- K7: scatter one-hot ------------------------------------------
__global__ void scatter_kernel(float* enc) {
    int row = blockIdx.x * blockDim.x + threadIdx.x;
    int stride = gridDim.x * blockDim.x;
    for (; row < NROWS; row += stride)
        enc[(size_t)row * KCODE + g_idx[row]] = 1.0f;
}

// ---------------- launch -------------------------------------------------------
extern "C" void kernel_launch(void* const* d_in, const int* in_sizes, int n_in,
                              void* d_out, int out_size) {
    const float* X = (const float*)d_in[0];
    const float* W = (const float*)d_in[1];
    if (n_in >= 2 && in_sizes[0] == KCODE * DIM && in_sizes[1] == NROWS * DIM) {
        X = (const float*)d_in[1];
        W = (const float*)d_in[0];
    }

    float* out = (float*)d_out;
    const long long FULL = 2LL + (long long)NROWS * DIM + (long long)NROWS * KCODE;

    float* loss_p = nullptr;
    float* q_p    = nullptr;
    float* perp_p = nullptr;
    float* enc_p  = nullptr;

    if ((long long)out_size == FULL) {
        loss_p = out;
        q_p    = out + 1;
        perp_p = out + 1 + (long long)NROWS * DIM;
        enc_p  = out + 2 + (long long)NROWS * DIM;
    } else if (out_size == NROWS * DIM) {
        q_p = out;
    } else if (out_size == NROWS * KCODE) {
        enc_p = out;
    } else if (out_size == 2) {
        loss_p = out;
        perp_p = out + 1;
    } else if (out_size == 1) {
        loss_p = out;
    } else {
        loss_p = out;
        if (out_size > 1 + NROWS * DIM) q_p = out + 1;
    }

    float* xn; cudaGetSymbolAddress((void**)&xn, g_xnorm);
    float* wn; cudaGetSymbolAddress((void**)&wn, g_wnorm);

    zero_counts_kernel<<<16, 256>>>();
    xla_norm_kernel<<<(NROWS * 4) / 256, 256>>>(X, xn, NROWS);
    xla_norm_kernel<<<(KCODE * 4) / 256, 256>>>(W, wn, KCODE);
    dist_argmin_kernel<<<NROWS / TMR, 256>>>(X, W);
    quantize_kernel<<<NROWS / 8, 256>>>(X, W, q_p);
    finalize_kernel<<<1, 1024>>>(loss_p, perp_p);
    if (enc_p) {
        long long n8 = (long long)NROWS * KCODE / 2;
        zero_enc_kernel<<<2048, 256>>>((unsigned long long*)enc_p, n8);
        scatter_kernel<<<128, 256>>>(enc_p);
    }
}

// round 7
// speedup vs baseline: 2.6582x; 2.0064x over previous
#include <cuda_runtime.h>
#include <cuda_bf16.h>
#include <math.h>
#include <stdint.h>

#define NROWS 32768
#define DIM   256
#define KCODE 4096

// dist kernel tiling
#define RT   128            // rows per CTA
#define CT   128            // codes per tile
#define NCT  (KCODE / CT)   // 32
#define KCH  32             // k per chunk
#define NKC  (DIM / KCH)    // 8

// smem layout (bytes)
#define SX_STR  264         // bf16 per X row (256 + 8 pad) -> stride%16==8 granules: conflict-free ldmatrix
#define SW_STR  40          // bf16 per W row (32 + 8 pad)
#define SD_STR  130         // floats per dist row
#define SX_OFF  0
#define SX_BYTES (128 * SX_STR * 2)            // 67584
#define SW_OFF  SX_BYTES
#define SW_BYTES (2 * 128 * SW_STR * 2)        // 20480
#define SD_OFF  (SW_OFF + SW_BYTES)            // 88064
#define SD_BYTES (128 * SD_STR * 4)            // 66560
#define WN_OFF  (SD_OFF + SD_BYTES)            // 154624
#define SMEM_TOT (WN_OFF + KCODE * 4)          // 171008

// ---------------- scratch ------------------------------------------------------
__device__ float  g_wnorm[KCODE];
__device__ float  g_xnorm[NROWS];
__device__ int    g_idx[NROWS];
__device__ int    g_cand[NROWS * 16];
__device__ int    g_counts[KCODE];
__device__ double g_part[NROWS / 8];

// ---------------- K1: zero counts ----------------------------------------------
__global__ void zero_counts_kernel() {
    int i = blockIdx.x * blockDim.x + threadIdx.x;
    if (i < KCODE) g_counts[i] = 0;
}

// ---------------- K2: XLA:CPU-emulated sum of squares (DO NOT TOUCH) -----------
__global__ void xla_norm_kernel(const float* __restrict__ A, float* __restrict__ out,
                                int nrows) {
    int gtid = blockIdx.x * blockDim.x + threadIdx.x;
    int row = gtid >> 2;
    int l = gtid & 3;
    if (row >= nrows) return;
    const float* r = A + (size_t)row * DIM;
    float a = 0.f;
    #pragma unroll 8
    for (int i = 0; i < DIM / 4; i++) {
        float v = __ldg(&r[4 * i + l]);
        a = __fadd_rn(a, __fmul_rn(v, v));
    }
    float b = __shfl_xor_sync(0xffffffffu, a, 2);
    float t = __fadd_rn(a, b);
    float c = __shfl_xor_sync(0xffffffffu, t, 1);
    float s = __fadd_rn(t, c);
    if (l == 0) out[row] = s;
}

// ---------------- K3: bf16 mma.sync candidate kernel ---------------------------
// 256 threads = 8 warps in 2m x 4n grid; warp tile 64 rows x 32 codes.
__global__ __launch_bounds__(256, 1)
void dist_topk_kernel(const float* __restrict__ X, const float* __restrict__ W) {
    extern __shared__ char smem[];
    __nv_bfloat16* sX = (__nv_bfloat16*)(smem + SX_OFF);
    __nv_bfloat16* sW = (__nv_bfloat16*)(smem + SW_OFF);
    float* sD  = (float*)(smem + SD_OFF);
    float* swn = (float*)(smem + WN_OFF);
    uint32_t sb  = (uint32_t)__cvta_generic_to_shared(smem);
    uint32_t sxb = sb + SX_OFF;
    uint32_t swb = sb + SW_OFF;

    const int tid  = threadIdx.x;
    const int lane = tid & 31;
    const int warp = tid >> 5;
    const int mw = warp & 1;
    const int nw = warp >> 1;
    const int rowBase = blockIdx.x * RT;

    const int sr = tid >> 1;    // staging/scan row or code 0..127
    const int sh = tid & 1;     // staging/scan half

    // ---- stage X (fp32 -> bf16) and wnorm into smem ----
    {
        const float4* src = (const float4*)(X + (size_t)(rowBase + sr) * DIM + sh * 128);
        __nv_bfloat162* dst = (__nv_bfloat162*)(sX + sr * SX_STR + sh * 128);
        #pragma unroll
        for (int i = 0; i < 32; i++) {
            float4 v = __ldg(&src[i]);
            dst[2 * i]     = __floats2bfloat162_rn(v.x, v.y);
            dst[2 * i + 1] = __floats2bfloat162_rn(v.z, v.w);
        }
        for (int i = tid; i < KCODE; i += 256) swn[i] = g_wnorm[i];
    }
    __syncthreads();

    // ldmatrix per-lane byte offsets
    const uint32_t aLane = (uint32_t)((lane & 15) * SX_STR * 2 + (lane >> 4) * 16);
    const uint32_t bLane = (uint32_t)((lane & 7) * SW_STR * 2 + ((lane >> 3) & 1) * 16);

    // running top-8 per thread (row = sr, code-half = sh)
    float tv[8];
    int   tix[8];
    #pragma unroll
    for (int i = 0; i < 8; i++) { tv[i] = 3.4e38f; tix[i] = 0; }
    float tmax = 3.4e38f;
    int tms = 0;

    float wreg[16];

    for (int ct = 0; ct < NCT; ct++) {
        const int n0 = ct * CT;
        const float* wsrc = W + (size_t)(n0 + sr) * DIM + sh * 16;

        // prefetch chunk 0
        #pragma unroll
        for (int q = 0; q < 4; q++) {
            float4 v = __ldg((const float4*)(wsrc) + q);
            wreg[4 * q] = v.x; wreg[4 * q + 1] = v.y;
            wreg[4 * q + 2] = v.z; wreg[4 * q + 3] = v.w;
        }

        float c[4][4][4];
        #pragma unroll
        for (int mt = 0; mt < 4; mt++)
            #pragma unroll
            for (int nt = 0; nt < 4; nt++)
                #pragma unroll
                for (int e = 0; e < 4; e++) c[mt][nt][e] = 0.f;

        int buf = 0;
        for (int kc = 0; kc < NKC; kc++) {
            // store prefetched chunk to sW[buf]
            {
                __nv_bfloat162* wd = (__nv_bfloat162*)(sW + buf * 128 * SW_STR + sr * SW_STR + sh * 16);
                #pragma unroll
                for (int q = 0; q < 8; q++)
                    wd[q] = __floats2bfloat162_rn(wreg[2 * q], wreg[2 * q + 1]);
            }
            __syncthreads();
            // prefetch next chunk
            if (kc + 1 < NKC) {
                const float4* ws = (const float4*)(wsrc + (kc + 1) * KCH);
                #pragma unroll
                for (int q = 0; q < 4; q++) {
                    float4 v = __ldg(&ws[q]);
                    wreg[4 * q] = v.x; wreg[4 * q + 1] = v.y;
                    wreg[4 * q + 2] = v.z; wreg[4 * q + 3] = v.w;
                }
            }
            // compute: 2 ksteps of 16
            #pragma unroll
            for (int ks = 0; ks < 2; ks++) {
                uint32_t a[4][4], b[4][2];
                #pragma unroll
                for (int mt = 0; mt < 4; mt++) {
                    uint32_t ad = sxb + (uint32_t)((mw * 64 + mt * 16) * SX_STR * 2
                                + (kc * KCH + ks * 16) * 2) + aLane;
                    asm volatile("ldmatrix.sync.aligned.m8n8.x4.shared.b16 {%0,%1,%2,%3},[%4];"
                                 : "=r"(a[mt][0]), "=r"(a[mt][1]), "=r"(a[mt][2]), "=r"(a[mt][3])
                                 : "r"(ad));
                }
                #pragma unroll
                for (int nt = 0; nt < 4; nt++) {
                    uint32_t bd = swb + (uint32_t)(buf * 128 * SW_STR * 2
                                + (nw * 32 + nt * 8) * SW_STR * 2 + ks * 32) + bLane;
                    asm volatile("ldmatrix.sync.aligned.m8n8.x2.shared.b16 {%0,%1},[%2];"
                                 : "=r"(b[nt][0]), "=r"(b[nt][1]) : "r"(bd));
                }
                #pragma unroll
                for (int mt = 0; mt < 4; mt++)
                    #pragma unroll
                    for (int nt = 0; nt < 4; nt++)
                        asm volatile(
                            "mma.sync.aligned.m16n8k16.row.col.f32.bf16.bf16.f32 "
                            "{%0,%1,%2,%3},{%4,%5,%6,%7},{%8,%9},{%0,%1,%2,%3};"
                            : "+f"(c[mt][nt][0]), "+f"(c[mt][nt][1]),
                              "+f"(c[mt][nt][2]), "+f"(c[mt][nt][3])
                            : "r"(a[mt][0]), "r"(a[mt][1]), "r"(a[mt][2]), "r"(a[mt][3]),
                              "r"(b[nt][0]), "r"(b[nt][1]));
            }
            buf ^= 1;
        }

        // dump dots to sD
        #pragma unroll
        for (int mt = 0; mt < 4; mt++) {
            int r0 = mw * 64 + mt * 16 + (lane >> 2);
            #pragma unroll
            for (int nt = 0; nt < 4; nt++) {
                int cc = nw * 32 + nt * 8 + 2 * (lane & 3);
                *(float2*)&sD[r0 * SD_STR + cc]       = make_float2(c[mt][nt][0], c[mt][nt][1]);
                *(float2*)&sD[(r0 + 8) * SD_STR + cc] = make_float2(c[mt][nt][2], c[mt][nt][3]);
            }
        }
        __syncthreads();

        // scan: 2 threads per row, 64 codes each, running top-8
        {
            const float* rowp = &sD[sr * SD_STR + sh * 64];
            #pragma unroll 8
            for (int j = 0; j < 64; j++) {
                int code = n0 + sh * 64 + j;
                float d = fmaf(-2.0f, rowp[j], swn[code]);
                if (d < tmax) {
                    tv[tms] = d; tix[tms] = code;
                    tmax = tv[0]; tms = 0;
                    #pragma unroll
                    for (int i2 = 1; i2 < 8; i2++)
                        if (tv[i2] > tmax) { tmax = tv[i2]; tms = i2; }
                }
            }
        }
        __syncthreads();
    }

    // write 16 candidates per row
    {
        int base = (rowBase + sr) * 16 + sh * 8;
        #pragma unroll
        for (int i = 0; i < 8; i++) g_cand[base + i] = tix[i];
    }
}

// ---------------- K3b: exact rescore of 16 candidates per row ------------------
__global__ __launch_bounds__(256)
void rescore_kernel(const float* __restrict__ X, const float* __restrict__ W) {
    int tid = blockIdx.x * blockDim.x + threadIdx.x;
    int row = tid >> 4;
    int j = tid & 15;
    if (row >= NROWS) return;
    int k = g_cand[row * 16 + j];
    float xn = g_xnorm[row];
    float wn = g_wnorm[k];
    const float4* xr = (const float4*)(X + (size_t)row * DIM);
    const float4* wr = (const float4*)(W + (size_t)k * DIM);
    float dot = 0.f;
    #pragma unroll 16
    for (int i = 0; i < DIM / 4; i++) {
        float4 xv = __ldg(&xr[i]);
        float4 wv = __ldg(&wr[i]);
        dot = fmaf(xv.x, wv.x, dot);
        dot = fmaf(xv.y, wv.y, dot);
        dot = fmaf(xv.z, wv.z, dot);
        dot = fmaf(xv.w, wv.w, dot);
    }
    float T = __fadd_rn(xn, wn);
    float dist = __fadd_rn(T, __fmul_rn(-2.0f, dot));
    // min + lowest-index tie-break across 16 candidate lanes
    #pragma unroll
    for (int off = 8; off > 0; off >>= 1) {
        float ov = __shfl_xor_sync(0xffffffffu, dist, off);
        int   oi = __shfl_xor_sync(0xffffffffu, k, off);
        if (ov < dist || (ov == dist && oi < k)) { dist = ov; k = oi; }
    }
    if (j == 0) g_idx[row] = k;
}

// ---------------- K4: gather / quantized_st / loss partials / histogram --------
__global__ __launch_bounds__(256)
void quantize_kernel(const float* __restrict__ X, const float* __restrict__ W,
                     float* q_out) {
    __shared__ double sh[8];
    int warp = threadIdx.x >> 5;
    int lane = threadIdx.x & 31;
    int row = blockIdx.x * 8 + warp;
    int idx = g_idx[row];
    if (lane == 0) atomicAdd(&g_counts[idx], 1);

    const float* xr = X + (size_t)row * DIM;
    const float* wr = W + (size_t)idx * DIM;
    double s = 0.0;
    #pragma unroll
    for (int j = 0; j < 2; j++) {
        int d = lane * 8 + j * 4;
        float4 xv = *(const float4*)&xr[d];
        float4 wv = *(const float4*)&wr[d];
        float t0 = wv.x - xv.x, t1 = wv.y - xv.y, t2 = wv.z - xv.z, t3 = wv.w - xv.w;
        if (q_out) {
            float* o = q_out + (size_t)row * DIM + d;
            o[0] = xv.x + t0; o[1] = xv.y + t1; o[2] = xv.z + t2; o[3] = xv.w + t3;
        }
        s += (double)t0 * t0 + (double)t1 * t1 + (double)t2 * t2 + (double)t3 * t3;
    }
    #pragma unroll
    for (int o = 16; o > 0; o >>= 1) s += __shfl_down_sync(0xffffffffu, s, o);
    if (lane == 0) sh[warp] = s;
    __syncthreads();
    if (threadIdx.x == 0) {
        double t = 0.0;
        #pragma unroll
        for (int w = 0; w < 8; w++) t += sh[w];
        g_part[blockIdx.x] = t;
    }
}

// ---------------- K5: finalize loss + perplexity -------------------------------
__global__ void finalize_kernel(float* loss_out, float* perp_out) {
    __shared__ double sh[1024];
    int tid = threadIdx.x;
    double s = 0.0;
    for (int i = tid; i < NROWS / 8; i += 1024) s += g_part[i];
    sh[tid] = s;
    __syncthreads();
    for (int o = 512; o > 0; o >>= 1) {
        if (tid < o) sh[tid] += sh[tid + o];
        __syncthreads();
    }
    double total = sh[0];
    __syncthreads();

    double e = 0.0;
    for (int i = tid; i < KCODE; i += 1024) {
        double p = (double)g_counts[i] / (double)NROWS;
        e += p * log(p + 1e-10);
    }
    sh[tid] = e;
    __syncthreads();
    for (int o = 512; o > 0; o >>= 1) {
        if (tid < o) sh[tid] += sh[tid + o];
        __syncthreads();
    }
    if (tid == 0) {
        double mse = total / ((double)NROWS * (double)DIM);
        if (loss_out) *loss_out = (float)(1.25 * mse);
        if (perp_out) *perp_out = (float)exp(-sh[0]);
    }
}

// ---------------- K6: zero encodings -------------------------------------------
__global__ void zero_enc_kernel(unsigned long long* enc, long long n8) {
    long long i = (long long)blockIdx.x * blockDim.x + threadIdx.x;
    long long stride = (long long)gridDim.x * blockDim.x;
    for (; i < n8; i += stride) enc[i] = 0ull;
}

// ---------------- K7: scatter one-hot ------------------------------------------
__global__ void scatter_kernel(float* enc) {
    int row = blockIdx.x * blockDim.x + threadIdx.x;
    int stride = gridDim.x * blockDim.x;
    for (; row < NROWS; row += stride)
        enc[(size_t)row * KCODE + g_idx[row]] = 1.0f;
}

// ---------------- launch -------------------------------------------------------
extern "C" void kernel_launch(void* const* d_in, const int* in_sizes, int n_in,
                              void* d_out, int out_size) {
    const float* X = (const float*)d_in[0];
    const float* W = (const float*)d_in[1];
    if (n_in >= 2 && in_sizes[0] == KCODE * DIM && in_sizes[1] == NROWS * DIM) {
        X = (const float*)d_in[1];
        W = (const float*)d_in[0];
    }

    float* out = (float*)d_out;
    const long long FULL = 2LL + (long long)NROWS * DIM + (long long)NROWS * KCODE;

    float* loss_p = nullptr;
    float* q_p    = nullptr;
    float* perp_p = nullptr;
    float* enc_p  = nullptr;

    if ((long long)out_size == FULL) {
        loss_p = out;
        q_p    = out + 1;
        perp_p = out + 1 + (long long)NROWS * DIM;
        enc_p  = out + 2 + (long long)NROWS * DIM;
    } else if (out_size == NROWS * DIM) {
        q_p = out;
    } else if (out_size == NROWS * KCODE) {
        enc_p = out;
    } else if (out_size == 2) {
        loss_p = out;
        perp_p = out + 1;
    } else if (out_size == 1) {
        loss_p = out;
    } else {
        loss_p = out;
        if (out_size > 1 + NROWS * DIM) q_p = out + 1;
    }

    float* xn; cudaGetSymbolAddress((void**)&xn, g_xnorm);
    float* wn; cudaGetSymbolAddress((void**)&wn, g_wnorm);

    cudaFuncSetAttribute(dist_topk_kernel,
                         cudaFuncAttributeMaxDynamicSharedMemorySize, SMEM_TOT);

    zero_counts_kernel<<<16, 256>>>();
    xla_norm_kernel<<<(NROWS * 4) / 256, 256>>>(X, xn, NROWS);
    xla_norm_kernel<<<(KCODE * 4) / 256, 256>>>(W, wn, KCODE);
    dist_topk_kernel<<<NROWS / RT, 256, SMEM_TOT>>>(X, W);
    rescore_kernel<<<(NROWS * 16) / 256, 256>>>(X, W);
    quantize_kernel<<<NROWS / 8, 256>>>(X, W, q_p);
    finalize_kernel<<<1, 1024>>>(loss_p, perp_p);
    if (enc_p) {
        long long n8 = (long long)NROWS * KCODE / 2;
        zero_enc_kernel<<<2048, 256>>>((unsigned long long*)enc_p, n8);
        scatter_kernel<<<128, 256>>>(enc_p);
    }
}

// round 9
// speedup vs baseline: 3.9046x; 1.4688x over previous
#include <cuda_runtime.h>
#include <cuda_bf16.h>
#include <math.h>
#include <stdint.h>

#define NROWS 32768
#define DIM   256
#define KCODE 4096

// dist kernel tiling
#define RT   128            // rows per CTA
#define CT   128            // codes per tile
#define NCT  (KCODE / CT)   // 32
#define KCH  64             // k per chunk
#define NKC  (DIM / KCH)    // 4
#define NCHUNKS (NCT * NKC) // 128
#define NSTAGE 3

// smem layout (bf16 strides chosen for conflict-free ldmatrix)
#define SX_STR  264                           // bf16/row (528B = 33 granules)
#define SW_STR  72                            // bf16/row (144B = 9 granules)
#define SX_BYTES (128 * SX_STR * 2)           // 67584
#define SW_STAGE (128 * SW_STR * 2)           // 18432
#define SMEM_TOT (SX_BYTES + NSTAGE * SW_STAGE) // 122880

// ---------------- scratch ------------------------------------------------------
__device__ __nv_bfloat16 g_Xb[NROWS * DIM];
__device__ __nv_bfloat16 g_Wb[KCODE * DIM];
__device__ float  g_wnorm[KCODE];
__device__ float  g_xnorm[NROWS];
__device__ int    g_idx[NROWS];
__device__ int    g_cand[NROWS * 32];
__device__ int    g_counts[KCODE];
__device__ double g_part[NROWS / 8];

// ---------------- K0: fp32 -> bf16 preconvert ----------------------------------
__global__ void cvt_bf16_kernel(const float* __restrict__ in,
                                __nv_bfloat16* __restrict__ out, int n8) {
    int i = blockIdx.x * blockDim.x + threadIdx.x;
    if (i >= n8) return;
    float4 a = ((const float4*)in)[2 * i];
    float4 b = ((const float4*)in)[2 * i + 1];
    __nv_bfloat162 o[4];
    o[0] = __floats2bfloat162_rn(a.x, a.y);
    o[1] = __floats2bfloat162_rn(a.z, a.w);
    o[2] = __floats2bfloat162_rn(b.x, b.y);
    o[3] = __floats2bfloat162_rn(b.z, b.w);
    ((float4*)out)[i] = *(float4*)o;
}

// ---------------- K1: zero counts ----------------------------------------------
__global__ void zero_counts_kernel() {
    int i = blockIdx.x * blockDim.x + threadIdx.x;
    if (i < KCODE) g_counts[i] = 0;
}

// ---------------- K2: XLA:CPU-emulated sum of squares (DO NOT TOUCH) -----------
__global__ void xla_norm_kernel(const float* __restrict__ A, float* __restrict__ out,
                                int nrows) {
    int gtid = blockIdx.x * blockDim.x + threadIdx.x;
    int row = gtid >> 2;
    int l = gtid & 3;
    if (row >= nrows) return;
    const float* r = A + (size_t)row * DIM;
    float a = 0.f;
    #pragma unroll 8
    for (int i = 0; i < DIM / 4; i++) {
        float v = __ldg(&r[4 * i + l]);
        a = __fadd_rn(a, __fmul_rn(v, v));
    }
    float b = __shfl_xor_sync(0xffffffffu, a, 2);
    float t = __fadd_rn(a, b);
    float c = __shfl_xor_sync(0xffffffffu, t, 1);
    float s = __fadd_rn(t, c);
    if (l == 0) out[row] = s;
}

// ---------------- K3: bf16 mma.sync candidate kernel (pipelined) ---------------
// 256 threads = 8 warps, 2m x 4n; warp tile 64 rows x 32 codes.
// W streamed via 3-stage cp.async ring; epilogue fully in registers (top-2/thread).
__global__ __launch_bounds__(256, 1)
void dist_topk_kernel() {
    extern __shared__ char smem[];
    uint32_t sb  = (uint32_t)__cvta_generic_to_shared(smem);
    uint32_t sxb = sb;
    uint32_t swb = sb + SX_BYTES;

    const int tid  = threadIdx.x;
    const int lane = tid & 31;
    const int warp = tid >> 5;
    const int mw = warp & 1;
    const int nw = warp >> 1;
    const int rowBase = blockIdx.x * RT;

    // ---- issue X tile loads (bf16, 512B rows -> stride 528B smem) ----
    {
        const __nv_bfloat16* src = g_Xb + (size_t)rowBase * DIM;
        #pragma unroll
        for (int q = 0; q < 16; q++) {
            int id = q * 256 + tid;           // 0..4095 16B chunks
            int row = id >> 5;
            int c16 = id & 31;
            uint32_t dst = sxb + (uint32_t)(row * (SX_STR * 2) + c16 * 16);
            const void* g = src + (size_t)row * DIM + c16 * 8;
            asm volatile("cp.async.cg.shared.global [%0], [%1], 16;"
                         :: "r"(dst), "l"(g) : "memory");
        }
        asm volatile("cp.async.commit_group;" ::: "memory");
    }

    // ---- issue W chunks 0,1 ----
    #pragma unroll
    for (int s = 0; s < 2; s++) {
        int ct = s >> 2, kc = s & 3;
        const __nv_bfloat16* src = g_Wb + (size_t)(ct * CT) * DIM + kc * KCH;
        uint32_t dstb = swb + (uint32_t)((s % NSTAGE) * SW_STAGE);
        #pragma unroll
        for (int q = 0; q < 4; q++) {
            int id = q * 256 + tid;           // 0..1023 16B chunks
            int row = id >> 3;
            int c8 = id & 7;
            uint32_t dst = dstb + (uint32_t)(row * (SW_STR * 2) + c8 * 16);
            const void* g = src + (size_t)row * DIM + c8 * 8;
            asm volatile("cp.async.cg.shared.global [%0], [%1], 16;"
                         :: "r"(dst), "l"(g) : "memory");
        }
        asm volatile("cp.async.commit_group;" ::: "memory");
    }

    const uint32_t aLane = (uint32_t)((lane & 15) * (SX_STR * 2) + (lane >> 4) * 16);
    const uint32_t bLane = (uint32_t)((lane & 7) * (SW_STR * 2) + ((lane >> 3) & 1) * 16);

    // per-thread running top-2 per row (8 rows: [mt*2 + h])
    float tv0[8], tv1[8];
    int   ti0[8], ti1[8];
    #pragma unroll
    for (int r = 0; r < 8; r++) { tv0[r] = 3.4e38f; tv1[r] = 3.4e38f; ti0[r] = 0; ti1[r] = 0; }

    float c[4][4][4];

    for (int s = 0; s < NCHUNKS; s++) {
        const int ct = s >> 2;
        const int kc = s & 3;
        if (kc == 0) {
            #pragma unroll
            for (int mt = 0; mt < 4; mt++)
                #pragma unroll
                for (int nt = 0; nt < 4; nt++)
                    #pragma unroll
                    for (int e = 0; e < 4; e++) c[mt][nt][e] = 0.f;
        }

        // stage s ready when <=1 groups outstanding
        asm volatile("cp.async.wait_group 1;" ::: "memory");
        __syncthreads();

        // issue chunk s+2 (buffer freed by compute(s-1), guaranteed by the sync)
        if (s + 2 < NCHUNKS) {
            int s2 = s + 2;
            int ct2 = s2 >> 2, kc2 = s2 & 3;
            const __nv_bfloat16* src = g_Wb + (size_t)(ct2 * CT) * DIM + kc2 * KCH;
            uint32_t dstb = swb + (uint32_t)((s2 % NSTAGE) * SW_STAGE);
            #pragma unroll
            for (int q = 0; q < 4; q++) {
                int id = q * 256 + tid;
                int row = id >> 3;
                int c8 = id & 7;
                uint32_t dst = dstb + (uint32_t)(row * (SW_STR * 2) + c8 * 16);
                const void* g = src + (size_t)row * DIM + c8 * 8;
                asm volatile("cp.async.cg.shared.global [%0], [%1], 16;"
                             :: "r"(dst), "l"(g) : "memory");
            }
            asm volatile("cp.async.commit_group;" ::: "memory");
        } else {
            asm volatile("cp.async.commit_group;" ::: "memory");  // keep group count in step
        }

        // ---- compute chunk s: 4 ksteps of k16 ----
        uint32_t wstage = swb + (uint32_t)((s % NSTAGE) * SW_STAGE);
        #pragma unroll
        for (int ks = 0; ks < 4; ks++) {
            uint32_t a[4][4], b[4][2];
            #pragma unroll
            for (int mt = 0; mt < 4; mt++) {
                uint32_t ad = sxb + (uint32_t)((mw * 64 + mt * 16) * (SX_STR * 2)
                            + (kc * KCH + ks * 16) * 2) + aLane;
                asm volatile("ldmatrix.sync.aligned.m8n8.x4.shared.b16 {%0,%1,%2,%3},[%4];"
                             : "=r"(a[mt][0]), "=r"(a[mt][1]), "=r"(a[mt][2]), "=r"(a[mt][3])
                             : "r"(ad));
            }
            #pragma unroll
            for (int nt = 0; nt < 4; nt++) {
                uint32_t bd = wstage + (uint32_t)((nw * 32 + nt * 8) * (SW_STR * 2) + ks * 32) + bLane;
                asm volatile("ldmatrix.sync.aligned.m8n8.x2.shared.b16 {%0,%1},[%2];"
                             : "=r"(b[nt][0]), "=r"(b[nt][1]) : "r"(bd));
            }
            #pragma unroll
            for (int mt = 0; mt < 4; mt++)
                #pragma unroll
                for (int nt = 0; nt < 4; nt++)
                    asm volatile(
                        "mma.sync.aligned.m16n8k16.row.col.f32.bf16.bf16.f32 "
                        "{%0,%1,%2,%3},{%4,%5,%6,%7},{%8,%9},{%0,%1,%2,%3};"
                        : "+f"(c[mt][nt][0]), "+f"(c[mt][nt][1]),
                          "+f"(c[mt][nt][2]), "+f"(c[mt][nt][3])
                        : "r"(a[mt][0]), "r"(a[mt][1]), "r"(a[mt][2]), "r"(a[mt][3]),
                          "r"(b[nt][0]), "r"(b[nt][1]));
        }

        // ---- tile epilogue in registers ----
        if (kc == 3) {
            #pragma unroll
            for (int nt = 0; nt < 4; nt++) {
                int kb = ct * CT + nw * 32 + nt * 8 + 2 * (lane & 3);
                float2 wn2 = __ldg((const float2*)&g_wnorm[kb]);
                #pragma unroll
                for (int mt = 0; mt < 4; mt++) {
                    #pragma unroll
                    for (int h = 0; h < 2; h++) {
                        int r = mt * 2 + h;
                        float d0 = fmaf(-2.0f, c[mt][nt][2 * h], wn2.x);
                        if (d0 < tv1[r]) {
                            if (d0 < tv0[r]) { tv1[r] = tv0[r]; ti1[r] = ti0[r]; tv0[r] = d0; ti0[r] = kb; }
                            else             { tv1[r] = d0; ti1[r] = kb; }
                        }
                        float d1 = fmaf(-2.0f, c[mt][nt][2 * h + 1], wn2.y);
                        if (d1 < tv1[r]) {
                            if (d1 < tv0[r]) { tv1[r] = tv0[r]; ti1[r] = ti0[r]; tv0[r] = d1; ti0[r] = kb + 1; }
                            else             { tv1[r] = d1; ti1[r] = kb + 1; }
                        }
                    }
                }
            }
        }
    }
    asm volatile("cp.async.wait_group 0;" ::: "memory");

    // ---- write 32 candidates per row (16 threads x top-2) ----
    #pragma unroll
    for (int mt = 0; mt < 4; mt++) {
        #pragma unroll
        for (int h = 0; h < 2; h++) {
            int r = mt * 2 + h;
            int row = rowBase + mw * 64 + mt * 16 + (lane >> 2) + h * 8;
            int base = row * 32 + nw * 8 + (lane & 3) * 2;
            g_cand[base]     = ti0[r];
            g_cand[base + 1] = ti1[r];
        }
    }
}

// ---------------- K3b: exact rescore of 32 candidates per row ------------------
__global__ __launch_bounds__(256)
void rescore_kernel(const float* __restrict__ X, const float* __restrict__ W) {
    int row = blockIdx.x * 8 + (threadIdx.x >> 5);
    int lane = threadIdx.x & 31;
    if (row >= NROWS) return;
    int k = g_cand[row * 32 + lane];
    float xn = g_xnorm[row];
    float wn = g_wnorm[k];
    const float4* xr = (const float4*)(X + (size_t)row * DIM);
    const float4* wr = (const float4*)(W + (size_t)k * DIM);
    float dot = 0.f;
    #pragma unroll 16
    for (int i = 0; i < DIM / 4; i++) {
        float4 xv = __ldg(&xr[i]);
        float4 wv = __ldg(&wr[i]);
        dot = fmaf(xv.x, wv.x, dot);
        dot = fmaf(xv.y, wv.y, dot);
        dot = fmaf(xv.z, wv.z, dot);
        dot = fmaf(xv.w, wv.w, dot);
    }
    float T = __fadd_rn(xn, wn);
    float dist = __fadd_rn(T, __fmul_rn(-2.0f, dot));
    #pragma unroll
    for (int off = 16; off > 0; off >>= 1) {
        float ov = __shfl_xor_sync(0xffffffffu, dist, off);
        int   oi = __shfl_xor_sync(0xffffffffu, k, off);
        if (ov < dist || (ov == dist && oi < k)) { dist = ov; k = oi; }
    }
    if (lane == 0) g_idx[row] = k;
}

// ---------------- K4: gather / quantized_st / loss partials / histogram --------
__global__ __launch_bounds__(256)
void quantize_kernel(const float* __restrict__ X, const float* __restrict__ W,
                     float* q_out) {
    __shared__ double sh[8];
    int warp = threadIdx.x >> 5;
    int lane = threadIdx.x & 31;
    int row = blockIdx.x * 8 + warp;
    int idx = g_idx[row];
    if (lane == 0) atomicAdd(&g_counts[idx], 1);

    const float* xr = X + (size_t)row * DIM;
    const float* wr = W + (size_t)idx * DIM;
    double s = 0.0;
    #pragma unroll
    for (int j = 0; j < 2; j++) {
        int d = lane * 8 + j * 4;
        float4 xv = *(const float4*)&xr[d];
        float4 wv = *(const float4*)&wr[d];
        float t0 = wv.x - xv.x, t1 = wv.y - xv.y, t2 = wv.z - xv.z, t3 = wv.w - xv.w;
        if (q_out) {
            float* o = q_out + (size_t)row * DIM + d;
            o[0] = xv.x + t0; o[1] = xv.y + t1; o[2] = xv.z + t2; o[3] = xv.w + t3;
        }
        s += (double)t0 * t0 + (double)t1 * t1 + (double)t2 * t2 + (double)t3 * t3;
    }
    #pragma unroll
    for (int o = 16; o > 0; o >>= 1) s += __shfl_down_sync(0xffffffffu, s, o);
    if (lane == 0) sh[warp] = s;
    __syncthreads();
    if (threadIdx.x == 0) {
        double t = 0.0;
        #pragma unroll
        for (int w = 0; w < 8; w++) t += sh[w];
        g_part[blockIdx.x] = t;
    }
}

// ---------------- K5: finalize loss + perplexity -------------------------------
__global__ void finalize_kernel(float* loss_out, float* perp_out) {
    __shared__ double sh[1024];
    int tid = threadIdx.x;
    double s = 0.0;
    for (int i = tid; i < NROWS / 8; i += 1024) s += g_part[i];
    sh[tid] = s;
    __syncthreads();
    for (int o = 512; o > 0; o >>= 1) {
        if (tid < o) sh[tid] += sh[tid + o];
        __syncthreads();
    }
    double total = sh[0];
    __syncthreads();

    double e = 0.0;
    for (int i = tid; i < KCODE; i += 1024) {
        double p = (double)g_counts[i] / (double)NROWS;
        e += p * log(p + 1e-10);
    }
    sh[tid] = e;
    __syncthreads();
    for (int o = 512; o > 0; o >>= 1) {
        if (tid < o) sh[tid] += sh[tid + o];
        __syncthreads();
    }
    if (tid == 0) {
        double mse = total / ((double)NROWS * (double)DIM);
        if (loss_out) *loss_out = (float)(1.25 * mse);
        if (perp_out) *perp_out = (float)exp(-sh[0]);
    }
}

// ---------------- K6: zero encodings -------------------------------------------
__global__ void zero_enc_kernel(unsigned long long* enc, long long n8) {
    long long i = (long long)blockIdx.x * blockDim.x + threadIdx.x;
    long long stride = (long long)gridDim.x * blockDim.x;
    for (; i < n8; i += stride) enc[i] = 0ull;
}

// ---------------- K7: scatter one-hot ------------------------------------------
__global__ void scatter_kernel(float* enc) {
    int row = blockIdx.x * blockDim.x + threadIdx.x;
    int stride = gridDim.x * blockDim.x;
    for (; row < NROWS; row += stride)
        enc[(size_t)row * KCODE + g_idx[row]] = 1.0f;
}

// ---------------- launch -------------------------------------------------------
extern "C" void kernel_launch(void* const* d_in, const int* in_sizes, int n_in,
                              void* d_out, int out_size) {
    const float* X = (const float*)d_in[0];
    const float* W = (const float*)d_in[1];
    if (n_in >= 2 && in_sizes[0] == KCODE * DIM && in_sizes[1] == NROWS * DIM) {
        X = (const float*)d_in[1];
        W = (const float*)d_in[0];
    }

    float* out = (float*)d_out;
    const long long FULL = 2LL + (long long)NROWS * DIM + (long long)NROWS * KCODE;

    float* loss_p = nullptr;
    float* q_p    = nullptr;
    float* perp_p = nullptr;
    float* enc_p  = nullptr;

    if ((long long)out_size == FULL) {
        loss_p = out;
        q_p    = out + 1;
        perp_p = out + 1 + (long long)NROWS * DIM;
        enc_p  = out + 2 + (long long)NROWS * DIM;
    } else if (out_size == NROWS * DIM) {
        q_p = out;
    } else if (out_size == NROWS * KCODE) {
        enc_p = out;
    } else if (out_size == 2) {
        loss_p = out;
        perp_p = out + 1;
    } else if (out_size == 1) {
        loss_p = out;
    } else {
        loss_p = out;
        if (out_size > 1 + NROWS * DIM) q_p = out + 1;
    }

    float* xn; cudaGetSymbolAddress((void**)&xn, g_xnorm);
    float* wn; cudaGetSymbolAddress((void**)&wn, g_wnorm);
    __nv_bfloat16* xb; cudaGetSymbolAddress((void**)&xb, g_Xb);
    __nv_bfloat16* wb; cudaGetSymbolAddress((void**)&wb, g_Wb);

    cudaFuncSetAttribute(dist_topk_kernel,
                         cudaFuncAttributeMaxDynamicSharedMemorySize, SMEM_TOT);

    cvt_bf16_kernel<<<(NROWS * DIM / 8) / 256, 256>>>(X, xb, NROWS * DIM / 8);
    cvt_bf16_kernel<<<(KCODE * DIM / 8) / 256, 256>>>(W, wb, KCODE * DIM / 8);
    zero_counts_kernel<<<16, 256>>>();
    xla_norm_kernel<<<(NROWS * 4) / 256, 256>>>(X, xn, NROWS);
    xla_norm_kernel<<<(KCODE * 4) / 256, 256>>>(W, wn, KCODE);
    dist_topk_kernel<<<NROWS / RT, 256, SMEM_TOT>>>();
    rescore_kernel<<<NROWS / 8, 256>>>(X, W);
    quantize_kernel<<<NROWS / 8, 256>>>(X, W, q_p);
    finalize_kernel<<<1, 1024>>>(loss_p, perp_p);
    if (enc_p) {
        long long n8 = (long long)NROWS * KCODE / 2;
        zero_enc_kernel<<<2048, 256>>>((unsigned long long*)enc_p, n8);
        scatter_kernel<<<128, 256>>>(enc_p);
    }
}

// round 14
// speedup vs baseline: 4.2538x; 1.0894x over previous
#include <cuda_runtime.h>
#include <cuda_bf16.h>
#include <math.h>
#include <stdint.h>

#define NROWS 32768
#define DIM   256
#define KCODE 4096

// dist kernel tiling
#define RT   128            // rows per CTA
#define CT   128            // codes per tile
#define NCT  (KCODE / CT)   // 32
#define KCH  64             // k per chunk
#define NKC  (DIM / KCH)    // 4
#define NCHUNKS (NCT * NKC) // 128
#define NSTAGE 3
#define DTHREADS 512

// smem layout (bf16 strides chosen for conflict-free ldmatrix)
#define SX_STR  264                           // bf16/row (528B = 33 granules)
#define SW_STR  72                            // bf16/row (144B = 9 granules)
#define SX_BYTES (128 * SX_STR * 2)           // 67584
#define SW_STAGE (128 * SW_STR * 2)           // 18432
#define SMEM_TOT (SX_BYTES + NSTAGE * SW_STAGE) // 122880

// ---------------- scratch ------------------------------------------------------
__device__ __nv_bfloat16 g_Xb[NROWS * DIM];
__device__ __nv_bfloat16 g_Wb[KCODE * DIM];
__device__ float  g_wnorm[KCODE];
__device__ float  g_xnorm[NROWS];
__device__ int    g_cand[NROWS * 32];
__device__ int    g_counts[KCODE];
__device__ double g_part[NROWS / 8];

// ---------------- K0: fp32 -> bf16 preconvert ----------------------------------
__global__ void cvt_bf16_kernel(const float* __restrict__ in,
                                __nv_bfloat16* __restrict__ out, int n8) {
    int i = blockIdx.x * blockDim.x + threadIdx.x;
    if (i >= n8) return;
    float4 a = ((const float4*)in)[2 * i];
    float4 b = ((const float4*)in)[2 * i + 1];
    __nv_bfloat162 o[4];
    o[0] = __floats2bfloat162_rn(a.x, a.y);
    o[1] = __floats2bfloat162_rn(a.z, a.w);
    o[2] = __floats2bfloat162_rn(b.x, b.y);
    o[3] = __floats2bfloat162_rn(b.z, b.w);
    ((float4*)out)[i] = *(float4*)o;
}

// ---------------- K1: zero counts ----------------------------------------------
__global__ void zero_counts_kernel() {
    int i = blockIdx.x * blockDim.x + threadIdx.x;
    if (i < KCODE) g_counts[i] = 0;
}

// ---------------- K2: XLA:CPU-emulated sum of squares (DO NOT TOUCH) -----------
__global__ void xla_norm_kernel(const float* __restrict__ A, float* __restrict__ out,
                                int nrows) {
    int gtid = blockIdx.x * blockDim.x + threadIdx.x;
    int row = gtid >> 2;
    int l = gtid & 3;
    if (row >= nrows) return;
    const float* r = A + (size_t)row * DIM;
    float a = 0.f;
    #pragma unroll 8
    for (int i = 0; i < DIM / 4; i++) {
        float v = __ldg(&r[4 * i + l]);
        a = __fadd_rn(a, __fmul_rn(v, v));
    }
    float b = __shfl_xor_sync(0xffffffffu, a, 2);
    float t = __fadd_rn(a, b);
    float c = __shfl_xor_sync(0xffffffffu, t, 1);
    float s = __fadd_rn(t, c);
    if (l == 0) out[row] = s;
}

// ---------------- K3: bf16 mma.sync candidate kernel (512 thr, pipelined) ------
// 16 warps in 4m x 4n grid; warp tile 32 rows x 32 codes.
// Also zeroes the encodings output region with 8-BYTE stores (enc base is only
// 8-aligned: out + 2 + NROWS*DIM) in the DRAM-idle shadow of the MMA loop.
__global__ __launch_bounds__(DTHREADS, 1)
void dist_topk_kernel(unsigned long long* __restrict__ enc8, int do_enc) {
    extern __shared__ char smem[];
    uint32_t sb  = (uint32_t)__cvta_generic_to_shared(smem);
    uint32_t sxb = sb;
    uint32_t swb = sb + SX_BYTES;

    const int tid  = threadIdx.x;
    const int lane = tid & 31;
    const int warp = tid >> 5;
    const int mw = warp & 3;
    const int nw = warp >> 2;
    const int rowBase = blockIdx.x * RT;

    // 128 rows * 4096 floats = 2MB per CTA = 262144 ull; 4 ull/thread/chunk
    unsigned long long* encp = do_enc ? (enc8 + (size_t)blockIdx.x * 262144) : (unsigned long long*)0;

    // ---- issue X tile loads ----
    {
        const __nv_bfloat16* src = g_Xb + (size_t)rowBase * DIM;
        #pragma unroll
        for (int q = 0; q < 8; q++) {
            int id = q * DTHREADS + tid;      // 0..4095 16B chunks
            int row = id >> 5;
            int c16 = id & 31;
            uint32_t dst = sxb + (uint32_t)(row * (SX_STR * 2) + c16 * 16);
            const void* g = src + (size_t)row * DIM + c16 * 8;
            asm volatile("cp.async.cg.shared.global [%0], [%1], 16;"
                         :: "r"(dst), "l"(g) : "memory");
        }
        asm volatile("cp.async.commit_group;" ::: "memory");
    }

    // ---- issue W chunks 0,1 ----
    #pragma unroll
    for (int s = 0; s < 2; s++) {
        int ct = s >> 2, kc = s & 3;
        const __nv_bfloat16* src = g_Wb + (size_t)(ct * CT) * DIM + kc * KCH;
        uint32_t dstb = swb + (uint32_t)((s % NSTAGE) * SW_STAGE);
        #pragma unroll
        for (int q = 0; q < 2; q++) {
            int id = q * DTHREADS + tid;      // 0..1023 16B chunks
            int row = id >> 3;
            int c8 = id & 7;
            uint32_t dst = dstb + (uint32_t)(row * (SW_STR * 2) + c8 * 16);
            const void* g = src + (size_t)row * DIM + c8 * 8;
            asm volatile("cp.async.cg.shared.global [%0], [%1], 16;"
                         :: "r"(dst), "l"(g) : "memory");
        }
        asm volatile("cp.async.commit_group;" ::: "memory");
    }

    const uint32_t aLane = (uint32_t)((lane & 15) * (SX_STR * 2) + (lane >> 4) * 16);
    const uint32_t bLane = (uint32_t)((lane & 7) * (SW_STR * 2) + ((lane >> 3) & 1) * 16);

    // per-thread running top-2 per row (4 rows: [mt*2 + h])
    float tv0[4], tv1[4];
    int   ti0[4], ti1[4];
    #pragma unroll
    for (int r = 0; r < 4; r++) { tv0[r] = 3.4e38f; tv1[r] = 3.4e38f; ti0[r] = 0; ti1[r] = 0; }

    float c[2][4][4];

    for (int s = 0; s < NCHUNKS; s++) {
        const int ct = s >> 2;
        const int kc = s & 3;
        if (kc == 0) {
            #pragma unroll
            for (int mt = 0; mt < 2; mt++)
                #pragma unroll
                for (int nt = 0; nt < 4; nt++)
                    #pragma unroll
                    for (int e = 0; e < 4; e++) c[mt][nt][e] = 0.f;
        }

        asm volatile("cp.async.wait_group 1;" ::: "memory");
        __syncthreads();

        // issue chunk s+2
        if (s + 2 < NCHUNKS) {
            int s2 = s + 2;
            int ct2 = s2 >> 2, kc2 = s2 & 3;
            const __nv_bfloat16* src = g_Wb + (size_t)(ct2 * CT) * DIM + kc2 * KCH;
            uint32_t dstb = swb + (uint32_t)((s2 % NSTAGE) * SW_STAGE);
            #pragma unroll
            for (int q = 0; q < 2; q++) {
                int id = q * DTHREADS + tid;
                int row = id >> 3;
                int c8 = id & 7;
                uint32_t dst = dstb + (uint32_t)(row * (SW_STR * 2) + c8 * 16);
                const void* g = src + (size_t)row * DIM + c8 * 8;
                asm volatile("cp.async.cg.shared.global [%0], [%1], 16;"
                             :: "r"(dst), "l"(g) : "memory");
            }
            asm volatile("cp.async.commit_group;" ::: "memory");
        } else {
            asm volatile("cp.async.commit_group;" ::: "memory");
        }

        // zero 4 x 8B of the encodings output (absorbed into DRAM-idle time)
        if (encp) {
            size_t eb = (size_t)(4 * s) * DTHREADS + tid;
            encp[eb]                = 0ull;
            encp[eb + DTHREADS]     = 0ull;
            encp[eb + 2 * DTHREADS] = 0ull;
            encp[eb + 3 * DTHREADS] = 0ull;
        }

        // ---- compute chunk s ----
        uint32_t wstage = swb + (uint32_t)((s % NSTAGE) * SW_STAGE);
        #pragma unroll
        for (int ks = 0; ks < 4; ks++) {
            uint32_t a[2][4], b[4][2];
            #pragma unroll
            for (int mt = 0; mt < 2; mt++) {
                uint32_t ad = sxb + (uint32_t)((mw * 32 + mt * 16) * (SX_STR * 2)
                            + (kc * KCH + ks * 16) * 2) + aLane;
                asm volatile("ldmatrix.sync.aligned.m8n8.x4.shared.b16 {%0,%1,%2,%3},[%4];"
                             : "=r"(a[mt][0]), "=r"(a[mt][1]), "=r"(a[mt][2]), "=r"(a[mt][3])
                             : "r"(ad));
            }
            #pragma unroll
            for (int nt = 0; nt < 4; nt++) {
                uint32_t bd = wstage + (uint32_t)((nw * 32 + nt * 8) * (SW_STR * 2) + ks * 32) + bLane;
                asm volatile("ldmatrix.sync.aligned.m8n8.x2.shared.b16 {%0,%1},[%2];"
                             : "=r"(b[nt][0]), "=r"(b[nt][1]) : "r"(bd));
            }
            #pragma unroll
            for (int mt = 0; mt < 2; mt++)
                #pragma unroll
                for (int nt = 0; nt < 4; nt++)
                    asm volatile(
                        "mma.sync.aligned.m16n8k16.row.col.f32.bf16.bf16.f32 "
                        "{%0,%1,%2,%3},{%4,%5,%6,%7},{%8,%9},{%0,%1,%2,%3};"
                        : "+f"(c[mt][nt][0]), "+f"(c[mt][nt][1]),
                          "+f"(c[mt][nt][2]), "+f"(c[mt][nt][3])
                        : "r"(a[mt][0]), "r"(a[mt][1]), "r"(a[mt][2]), "r"(a[mt][3]),
                          "r"(b[nt][0]), "r"(b[nt][1]));
        }

        // ---- tile epilogue in registers ----
        if (kc == 3) {
            #pragma unroll
            for (int nt = 0; nt < 4; nt++) {
                int kb = ct * CT + nw * 32 + nt * 8 + 2 * (lane & 3);
                float2 wn2 = __ldg((const float2*)&g_wnorm[kb]);
                #pragma unroll
                for (int mt = 0; mt < 2; mt++) {
                    #pragma unroll
                    for (int h = 0; h < 2; h++) {
                        int r = mt * 2 + h;
                        float d0 = fmaf(-2.0f, c[mt][nt][2 * h], wn2.x);
                        if (d0 < tv1[r]) {
                            if (d0 < tv0[r]) { tv1[r] = tv0[r]; ti1[r] = ti0[r]; tv0[r] = d0; ti0[r] = kb; }
                            else             { tv1[r] = d0; ti1[r] = kb; }
                        }
                        float d1 = fmaf(-2.0f, c[mt][nt][2 * h + 1], wn2.y);
                        if (d1 < tv1[r]) {
                            if (d1 < tv0[r]) { tv1[r] = tv0[r]; ti1[r] = ti0[r]; tv0[r] = d1; ti0[r] = kb + 1; }
                            else             { tv1[r] = d1; ti1[r] = kb + 1; }
                        }
                    }
                }
            }
        }
    }
    asm volatile("cp.async.wait_group 0;" ::: "memory");

    // ---- write 32 candidates per row (16 threads x top-2) ----
    #pragma unroll
    for (int mt = 0; mt < 2; mt++) {
        #pragma unroll
        for (int h = 0; h < 2; h++) {
            int r = mt * 2 + h;
            int row = rowBase + mw * 32 + mt * 16 + (lane >> 2) + h * 8;
            int base = row * 32 + nw * 8 + (lane & 3) * 2;
            g_cand[base]     = ti0[r];
            g_cand[base + 1] = ti1[r];
        }
    }
}

// ---------------- K4: fused rescore + quantize + scatter + histogram -----------
__global__ __launch_bounds__(256)
void fused_assign_kernel(const float* __restrict__ X, const float* __restrict__ W,
                         float* q_out, float* enc) {
    __shared__ double sh[8];
    int warp = threadIdx.x >> 5;
    int lane = threadIdx.x & 31;
    int row = blockIdx.x * 8 + warp;

    int k = g_cand[row * 32 + lane];
    float xn = g_xnorm[row];
    float wn = g_wnorm[k];
    const float4* xr4 = (const float4*)(X + (size_t)row * DIM);
    const float4* wr4 = (const float4*)(W + (size_t)k * DIM);
    float dot = 0.f;
    #pragma unroll 16
    for (int i = 0; i < DIM / 4; i++) {
        float4 xv = __ldg(&xr4[i]);
        float4 wv = __ldg(&wr4[i]);
        dot = fmaf(xv.x, wv.x, dot);
        dot = fmaf(xv.y, wv.y, dot);
        dot = fmaf(xv.z, wv.z, dot);
        dot = fmaf(xv.w, wv.w, dot);
    }
    float T = __fadd_rn(xn, wn);
    float dist = __fadd_rn(T, __fmul_rn(-2.0f, dot));
    #pragma unroll
    for (int off = 16; off > 0; off >>= 1) {
        float ov = __shfl_xor_sync(0xffffffffu, dist, off);
        int   oi = __shfl_xor_sync(0xffffffffu, k, off);
        if (ov < dist || (ov == dist && oi < k)) { dist = ov; k = oi; }
    }
    // all lanes now hold the winning k
    if (lane == 0) {
        atomicAdd(&g_counts[k], 1);
        if (enc) enc[(size_t)row * KCODE + k] = 1.0f;
    }

    const float* xr = X + (size_t)row * DIM;
    const float* wr = W + (size_t)k * DIM;
    double s = 0.0;
    #pragma unroll
    for (int j = 0; j < 2; j++) {
        int d = lane * 8 + j * 4;
        float4 xv = *(const float4*)&xr[d];
        float4 wv = *(const float4*)&wr[d];
        float t0 = wv.x - xv.x, t1 = wv.y - xv.y, t2 = wv.z - xv.z, t3 = wv.w - xv.w;
        if (q_out) {
            float* o = q_out + (size_t)row * DIM + d;
            o[0] = xv.x + t0; o[1] = xv.y + t1; o[2] = xv.z + t2; o[3] = xv.w + t3;
        }
        s += (double)t0 * t0 + (double)t1 * t1 + (double)t2 * t2 + (double)t3 * t3;
    }
    #pragma unroll
    for (int o = 16; o > 0; o >>= 1) s += __shfl_down_sync(0xffffffffu, s, o);
    if (lane == 0) sh[warp] = s;
    __syncthreads();
    if (threadIdx.x == 0) {
        double t = 0.0;
        #pragma unroll
        for (int w = 0; w < 8; w++) t += sh[w];
        g_part[blockIdx.x] = t;
    }
}

// ---------------- K5: finalize loss + perplexity -------------------------------
__global__ void finalize_kernel(float* loss_out, float* perp_out) {
    __shared__ double sh[1024];
    int tid = threadIdx.x;
    double s = 0.0;
    for (int i = tid; i < NROWS / 8; i += 1024) s += g_part[i];
    sh[tid] = s;
    __syncthreads();
    for (int o = 512; o > 0; o >>= 1) {
        if (tid < o) sh[tid] += sh[tid + o];
        __syncthreads();
    }
    double total = sh[0];
    __syncthreads();

    double e = 0.0;
    for (int i = tid; i < KCODE; i += 1024) {
        double p = (double)g_counts[i] / (double)NROWS;
        e += p * log(p + 1e-10);
    }
    sh[tid] = e;
    __syncthreads();
    for (int o = 512; o > 0; o >>= 1) {
        if (tid < o) sh[tid] += sh[tid + o];
        __syncthreads();
    }
    if (tid == 0) {
        double mse = total / ((double)NROWS * (double)DIM);
        if (loss_out) *loss_out = (float)(1.25 * mse);
        if (perp_out) *perp_out = (float)exp(-sh[0]);
    }
}

// ---------------- launch -------------------------------------------------------
extern "C" void kernel_launch(void* const* d_in, const int* in_sizes, int n_in,
                              void* d_out, int out_size) {
    const float* X = (const float*)d_in[0];
    const float* W = (const float*)d_in[1];
    if (n_in >= 2 && in_sizes[0] == KCODE * DIM && in_sizes[1] == NROWS * DIM) {
        X = (const float*)d_in[1];
        W = (const float*)d_in[0];
    }

    float* out = (float*)d_out;
    const long long FULL = 2LL + (long long)NROWS * DIM + (long long)NROWS * KCODE;

    float* loss_p = nullptr;
    float* q_p    = nullptr;
    float* perp_p = nullptr;
    float* enc_p  = nullptr;

    if ((long long)out_size == FULL) {
        loss_p = out;
        q_p    = out + 1;
        perp_p = out + 1 + (long long)NROWS * DIM;
        enc_p  = out + 2 + (long long)NROWS * DIM;
    } else if (out_size == NROWS * DIM) {
        q_p = out;
    } else if (out_size == NROWS * KCODE) {
        enc_p = out;
    } else if (out_size == 2) {
        loss_p = out;
        perp_p = out + 1;
    } else if (out_size == 1) {
        loss_p = out;
    } else {
        loss_p = out;
        if (out_size > 1 + NROWS * DIM) q_p = out + 1;
    }

    float* xn; cudaGetSymbolAddress((void**)&xn, g_xnorm);
    float* wn; cudaGetSymbolAddress((void**)&wn, g_wnorm);
    __nv_bfloat16* xb; cudaGetSymbolAddress((void**)&xb, g_Xb);
    __nv_bfloat16* wb; cudaGetSymbolAddress((void**)&wb, g_Wb);

    cudaFuncSetAttribute(dist_topk_kernel,
                         cudaFuncAttributeMaxDynamicSharedMemorySize, SMEM_TOT);

    cvt_bf16_kernel<<<(NROWS * DIM / 8) / 256, 256>>>(X, xb, NROWS * DIM / 8);
    cvt_bf16_kernel<<<(KCODE * DIM / 8) / 256, 256>>>(W, wb, KCODE * DIM / 8);
    zero_counts_kernel<<<16, 256>>>();
    xla_norm_kernel<<<(NROWS * 4) / 256, 256>>>(X, xn, NROWS);
    xla_norm_kernel<<<(KCODE * 4) / 256, 256>>>(W, wn, KCODE);
    dist_topk_kernel<<<NROWS / RT, DTHREADS, SMEM_TOT>>>((unsigned long long*)enc_p, enc_p != nullptr);
    fused_assign_kernel<<<NROWS / 8, 256>>>(X, W, q_p, enc_p);
    finalize_kernel<<<1, 1024>>>(loss_p, perp_p);
}

// round 15
// speedup vs baseline: 4.4070x; 1.0360x over previous
#include <cuda_runtime.h>
#include <cuda_bf16.h>
#include <math.h>
#include <stdint.h>

#define NROWS 32768
#define DIM   256
#define KCODE 4096

// dist kernel tiling
#define RT   128            // rows per CTA
#define CT   128            // codes per tile
#define NCT  (KCODE / CT)   // 32
#define KCH  128            // k per chunk (half tile k-depth = full 128)
#define NKC  (DIM / KCH)    // 2
#define NCHUNKS (NCT * NKC) // 64
#define NSTAGE 3
#define DTHREADS 512

// smem layout (bf16 strides chosen for conflict-free ldmatrix)
#define SX_STR  264                           // bf16/row (528B; 528%128==16)
#define SW_STR  136                           // bf16/row (272B; 272%128==16)
#define SX_BYTES (128 * SX_STR * 2)           // 67584
#define SW_STAGE (128 * SW_STR * 2)           // 34816
#define SMEM_TOT (SX_BYTES + NSTAGE * SW_STAGE) // 172032

// ---------------- scratch ------------------------------------------------------
__device__ __nv_bfloat16 g_Xb[NROWS * DIM];
__device__ __nv_bfloat16 g_Wb[KCODE * DIM];
__device__ float  g_wnorm[KCODE];
__device__ float  g_xnorm[NROWS];
__device__ int    g_cand[NROWS * 32];
__device__ int    g_counts[KCODE];
__device__ double g_part[NROWS / 8];

// ---------------- K0: fp32 -> bf16 preconvert ----------------------------------
__global__ void cvt_bf16_kernel(const float* __restrict__ in,
                                __nv_bfloat16* __restrict__ out, int n8) {
    int i = blockIdx.x * blockDim.x + threadIdx.x;
    if (i >= n8) return;
    float4 a = ((const float4*)in)[2 * i];
    float4 b = ((const float4*)in)[2 * i + 1];
    __nv_bfloat162 o[4];
    o[0] = __floats2bfloat162_rn(a.x, a.y);
    o[1] = __floats2bfloat162_rn(a.z, a.w);
    o[2] = __floats2bfloat162_rn(b.x, b.y);
    o[3] = __floats2bfloat162_rn(b.z, b.w);
    ((float4*)out)[i] = *(float4*)o;
}

// ---------------- K1: zero counts ----------------------------------------------
__global__ void zero_counts_kernel() {
    int i = blockIdx.x * blockDim.x + threadIdx.x;
    if (i < KCODE) g_counts[i] = 0;
}

// ---------------- K2: XLA:CPU-emulated sum of squares (DO NOT TOUCH) -----------
__global__ void xla_norm_kernel(const float* __restrict__ A, float* __restrict__ out,
                                int nrows) {
    int gtid = blockIdx.x * blockDim.x + threadIdx.x;
    int row = gtid >> 2;
    int l = gtid & 3;
    if (row >= nrows) return;
    const float* r = A + (size_t)row * DIM;
    float a = 0.f;
    #pragma unroll 8
    for (int i = 0; i < DIM / 4; i++) {
        float v = __ldg(&r[4 * i + l]);
        a = __fadd_rn(a, __fmul_rn(v, v));
    }
    float b = __shfl_xor_sync(0xffffffffu, a, 2);
    float t = __fadd_rn(a, b);
    float c = __shfl_xor_sync(0xffffffffu, t, 1);
    float s = __fadd_rn(t, c);
    if (l == 0) out[row] = s;
}

// ---------------- K3: bf16 mma.sync candidate kernel (512 thr, 128-k chunks) ---
// 16 warps in 4m x 4n grid; warp tile 32 rows x 32 codes.
// Zeroes the encodings output (8-byte stores; enc base is 8-aligned) in the
// DRAM-idle shadow of the MMA loop.
__global__ __launch_bounds__(DTHREADS, 1)
void dist_topk_kernel(unsigned long long* __restrict__ enc8, int do_enc) {
    extern __shared__ char smem[];
    uint32_t sb  = (uint32_t)__cvta_generic_to_shared(smem);
    uint32_t sxb = sb;
    uint32_t swb = sb + SX_BYTES;

    const int tid  = threadIdx.x;
    const int lane = tid & 31;
    const int warp = tid >> 5;
    const int mw = warp & 3;
    const int nw = warp >> 2;
    const int rowBase = blockIdx.x * RT;

    // 2MB per CTA = 262144 ull; 8 ull/thread/chunk * 64 chunks * 512 thr
    unsigned long long* encp = do_enc ? (enc8 + (size_t)blockIdx.x * 262144) : (unsigned long long*)0;

    // ---- issue X tile loads ----
    {
        const __nv_bfloat16* src = g_Xb + (size_t)rowBase * DIM;
        #pragma unroll
        for (int q = 0; q < 8; q++) {
            int id = q * DTHREADS + tid;      // 0..4095 16B chunks
            int row = id >> 5;
            int c16 = id & 31;
            uint32_t dst = sxb + (uint32_t)(row * (SX_STR * 2) + c16 * 16);
            const void* g = src + (size_t)row * DIM + c16 * 8;
            asm volatile("cp.async.cg.shared.global [%0], [%1], 16;"
                         :: "r"(dst), "l"(g) : "memory");
        }
        asm volatile("cp.async.commit_group;" ::: "memory");
    }

    // ---- issue W chunks 0,1 ----
    #pragma unroll
    for (int s = 0; s < 2; s++) {
        int ct = s >> 1, kc = s & 1;
        const __nv_bfloat16* src = g_Wb + (size_t)(ct * CT) * DIM + kc * KCH;
        uint32_t dstb = swb + (uint32_t)((s % NSTAGE) * SW_STAGE);
        #pragma unroll
        for (int q = 0; q < 4; q++) {
            int id = q * DTHREADS + tid;      // 0..2047 16B chunks
            int row = id >> 4;
            int c16 = id & 15;
            uint32_t dst = dstb + (uint32_t)(row * (SW_STR * 2) + c16 * 16);
            const void* g = src + (size_t)row * DIM + c16 * 8;
            asm volatile("cp.async.cg.shared.global [%0], [%1], 16;"
                         :: "r"(dst), "l"(g) : "memory");
        }
        asm volatile("cp.async.commit_group;" ::: "memory");
    }

    const uint32_t aLane = (uint32_t)((lane & 15) * (SX_STR * 2) + (lane >> 4) * 16);
    const uint32_t bLane = (uint32_t)((lane & 7) * (SW_STR * 2) + ((lane >> 3) & 1) * 16);

    // per-thread running top-2 per row (4 rows: [mt*2 + h])
    float tv0[4], tv1[4];
    int   ti0[4], ti1[4];
    #pragma unroll
    for (int r = 0; r < 4; r++) { tv0[r] = 3.4e38f; tv1[r] = 3.4e38f; ti0[r] = 0; ti1[r] = 0; }

    float c[2][4][4];

    for (int s = 0; s < NCHUNKS; s++) {
        const int ct = s >> 1;
        const int kc = s & 1;
        if (kc == 0) {
            #pragma unroll
            for (int mt = 0; mt < 2; mt++)
                #pragma unroll
                for (int nt = 0; nt < 4; nt++)
                    #pragma unroll
                    for (int e = 0; e < 4; e++) c[mt][nt][e] = 0.f;
        }

        asm volatile("cp.async.wait_group 1;" ::: "memory");
        __syncthreads();

        // issue chunk s+2 (slot freed: compute(s-1) finished before this barrier)
        if (s + 2 < NCHUNKS) {
            int s2 = s + 2;
            int ct2 = s2 >> 1, kc2 = s2 & 1;
            const __nv_bfloat16* src = g_Wb + (size_t)(ct2 * CT) * DIM + kc2 * KCH;
            uint32_t dstb = swb + (uint32_t)((s2 % NSTAGE) * SW_STAGE);
            #pragma unroll
            for (int q = 0; q < 4; q++) {
                int id = q * DTHREADS + tid;
                int row = id >> 4;
                int c16 = id & 15;
                uint32_t dst = dstb + (uint32_t)(row * (SW_STR * 2) + c16 * 16);
                const void* g = src + (size_t)row * DIM + c16 * 8;
                asm volatile("cp.async.cg.shared.global [%0], [%1], 16;"
                             :: "r"(dst), "l"(g) : "memory");
            }
            asm volatile("cp.async.commit_group;" ::: "memory");
        } else {
            asm volatile("cp.async.commit_group;" ::: "memory");
        }

        // zero 8 x 8B of the encodings output (absorbed into DRAM-idle time)
        if (encp) {
            size_t eb = (size_t)(8 * s) * DTHREADS + tid;
            #pragma unroll
            for (int z = 0; z < 8; z++) encp[eb + (size_t)z * DTHREADS] = 0ull;
        }

        // ---- compute chunk s: 8 ksteps of k16 ----
        uint32_t wstage = swb + (uint32_t)((s % NSTAGE) * SW_STAGE);
        #pragma unroll
        for (int ks = 0; ks < 8; ks++) {
            uint32_t a[2][4], b[4][2];
            #pragma unroll
            for (int mt = 0; mt < 2; mt++) {
                uint32_t ad = sxb + (uint32_t)((mw * 32 + mt * 16) * (SX_STR * 2)
                            + (kc * KCH + ks * 16) * 2) + aLane;
                asm volatile("ldmatrix.sync.aligned.m8n8.x4.shared.b16 {%0,%1,%2,%3},[%4];"
                             : "=r"(a[mt][0]), "=r"(a[mt][1]), "=r"(a[mt][2]), "=r"(a[mt][3])
                             : "r"(ad));
            }
            #pragma unroll
            for (int nt = 0; nt < 4; nt++) {
                uint32_t bd = wstage + (uint32_t)((nw * 32 + nt * 8) * (SW_STR * 2) + ks * 32) + bLane;
                asm volatile("ldmatrix.sync.aligned.m8n8.x2.shared.b16 {%0,%1},[%2];"
                             : "=r"(b[nt][0]), "=r"(b[nt][1]) : "r"(bd));
            }
            #pragma unroll
            for (int mt = 0; mt < 2; mt++)
                #pragma unroll
                for (int nt = 0; nt < 4; nt++)
                    asm volatile(
                        "mma.sync.aligned.m16n8k16.row.col.f32.bf16.bf16.f32 "
                        "{%0,%1,%2,%3},{%4,%5,%6,%7},{%8,%9},{%0,%1,%2,%3};"
                        : "+f"(c[mt][nt][0]), "+f"(c[mt][nt][1]),
                          "+f"(c[mt][nt][2]), "+f"(c[mt][nt][3])
                        : "r"(a[mt][0]), "r"(a[mt][1]), "r"(a[mt][2]), "r"(a[mt][3]),
                          "r"(b[nt][0]), "r"(b[nt][1]));
        }

        // ---- tile epilogue in registers ----
        if (kc == 1) {
            #pragma unroll
            for (int nt = 0; nt < 4; nt++) {
                int kb = ct * CT + nw * 32 + nt * 8 + 2 * (lane & 3);
                float2 wn2 = __ldg((const float2*)&g_wnorm[kb]);
                #pragma unroll
                for (int mt = 0; mt < 2; mt++) {
                    #pragma unroll
                    for (int h = 0; h < 2; h++) {
                        int r = mt * 2 + h;
                        float d0 = fmaf(-2.0f, c[mt][nt][2 * h], wn2.x);
                        if (d0 < tv1[r]) {
                            if (d0 < tv0[r]) { tv1[r] = tv0[r]; ti1[r] = ti0[r]; tv0[r] = d0; ti0[r] = kb; }
                            else             { tv1[r] = d0; ti1[r] = kb; }
                        }
                        float d1 = fmaf(-2.0f, c[mt][nt][2 * h + 1], wn2.y);
                        if (d1 < tv1[r]) {
                            if (d1 < tv0[r]) { tv1[r] = tv0[r]; ti1[r] = ti0[r]; tv0[r] = d1; ti0[r] = kb + 1; }
                            else             { tv1[r] = d1; ti1[r] = kb + 1; }
                        }
                    }
                }
            }
        }
    }
    asm volatile("cp.async.wait_group 0;" ::: "memory");

    // ---- write 32 candidates per row (16 threads x top-2) ----
    #pragma unroll
    for (int mt = 0; mt < 2; mt++) {
        #pragma unroll
        for (int h = 0; h < 2; h++) {
            int r = mt * 2 + h;
            int row = rowBase + mw * 32 + mt * 16 + (lane >> 2) + h * 8;
            int base = row * 32 + nw * 8 + (lane & 3) * 2;
            g_cand[base]     = ti0[r];
            g_cand[base + 1] = ti1[r];
        }
    }
}

// ---------------- K4: fused rescore + quantize + scatter + histogram -----------
__global__ __launch_bounds__(256)
void fused_assign_kernel(const float* __restrict__ X, const float* __restrict__ W,
                         float* q_out, float* enc) {
    __shared__ double sh[8];
    int warp = threadIdx.x >> 5;
    int lane = threadIdx.x & 31;
    int row = blockIdx.x * 8 + warp;

    int k = g_cand[row * 32 + lane];
    float xn = g_xnorm[row];
    float wn = g_wnorm[k];
    const float4* xr4 = (const float4*)(X + (size_t)row * DIM);
    const float4* wr4 = (const float4*)(W + (size_t)k * DIM);
    float dot = 0.f;
    #pragma unroll 16
    for (int i = 0; i < DIM / 4; i++) {
        float4 xv = __ldg(&xr4[i]);
        float4 wv = __ldg(&wr4[i]);
        dot = fmaf(xv.x, wv.x, dot);
        dot = fmaf(xv.y, wv.y, dot);
        dot = fmaf(xv.z, wv.z, dot);
        dot = fmaf(xv.w, wv.w, dot);
    }
    float T = __fadd_rn(xn, wn);
    float dist = __fadd_rn(T, __fmul_rn(-2.0f, dot));
    #pragma unroll
    for (int off = 16; off > 0; off >>= 1) {
        float ov = __shfl_xor_sync(0xffffffffu, dist, off);
        int   oi = __shfl_xor_sync(0xffffffffu, k, off);
        if (ov < dist || (ov == dist && oi < k)) { dist = ov; k = oi; }
    }
    // all lanes now hold the winning k
    if (lane == 0) {
        atomicAdd(&g_counts[k], 1);
        if (enc) enc[(size_t)row * KCODE + k] = 1.0f;
    }

    const float* xr = X + (size_t)row * DIM;
    const float* wr = W + (size_t)k * DIM;
    double s = 0.0;
    #pragma unroll
    for (int j = 0; j < 2; j++) {
        int d = lane * 8 + j * 4;
        float4 xv = *(const float4*)&xr[d];
        float4 wv = *(const float4*)&wr[d];
        float t0 = wv.x - xv.x, t1 = wv.y - xv.y, t2 = wv.z - xv.z, t3 = wv.w - xv.w;
        if (q_out) {
            float* o = q_out + (size_t)row * DIM + d;
            o[0] = xv.x + t0; o[1] = xv.y + t1; o[2] = xv.z + t2; o[3] = xv.w + t3;
        }
        s += (double)t0 * t0 + (double)t1 * t1 + (double)t2 * t2 + (double)t3 * t3;
    }
    #pragma unroll
    for (int o = 16; o > 0; o >>= 1) s += __shfl_down_sync(0xffffffffu, s, o);
    if (lane == 0) sh[warp] = s;
    __syncthreads();
    if (threadIdx.x == 0) {
        double t = 0.0;
        #pragma unroll
        for (int w = 0; w < 8; w++) t += sh[w];
        g_part[blockIdx.x] = t;
    }
}

// ---------------- K5: finalize loss + perplexity -------------------------------
__global__ void finalize_kernel(float* loss_out, float* perp_out) {
    __shared__ double sh[1024];
    int tid = threadIdx.x;
    double s = 0.0;
    for (int i = tid; i < NROWS / 8; i += 1024) s += g_part[i];
    sh[tid] = s;
    __syncthreads();
    for (int o = 512; o > 0; o >>= 1) {
        if (tid < o) sh[tid] += sh[tid + o];
        __syncthreads();
    }
    double total = sh[0];
    __syncthreads();

    double e = 0.0;
    for (int i = tid; i < KCODE; i += 1024) {
        double p = (double)g_counts[i] / (double)NROWS;
        e += p * log(p + 1e-10);
    }
    sh[tid] = e;
    __syncthreads();
    for (int o = 512; o > 0; o >>= 1) {
        if (tid < o) sh[tid] += sh[tid + o];
        __syncthreads();
    }
    if (tid == 0) {
        double mse = total / ((double)NROWS * (double)DIM);
        if (loss_out) *loss_out = (float)(1.25 * mse);
        if (perp_out) *perp_out = (float)exp(-sh[0]);
    }
}

// ---------------- launch -------------------------------------------------------
extern "C" void kernel_launch(void* const* d_in, const int* in_sizes, int n_in,
                              void* d_out, int out_size) {
    const float* X = (const float*)d_in[0];
    const float* W = (const float*)d_in[1];
    if (n_in >= 2 && in_sizes[0] == KCODE * DIM && in_sizes[1] == NROWS * DIM) {
        X = (const float*)d_in[1];
        W = (const float*)d_in[0];
    }

    float* out = (float*)d_out;
    const long long FULL = 2LL + (long long)NROWS * DIM + (long long)NROWS * KCODE;

    float* loss_p = nullptr;
    float* q_p    = nullptr;
    float* perp_p = nullptr;
    float* enc_p  = nullptr;

    if ((long long)out_size == FULL) {
        loss_p = out;
        q_p    = out + 1;
        perp_p = out + 1 + (long long)NROWS * DIM;
        enc_p  = out + 2 + (long long)NROWS * DIM;
    } else if (out_size == NROWS * DIM) {
        q_p = out;
    } else if (out_size == NROWS * KCODE) {
        enc_p = out;
    } else if (out_size == 2) {
        loss_p = out;
        perp_p = out + 1;
    } else if (out_size == 1) {
        loss_p = out;
    } else {
        loss_p = out;
        if (out_size > 1 + NROWS * DIM) q_p = out + 1;
    }

    float* xn; cudaGetSymbolAddress((void**)&xn, g_xnorm);
    float* wn; cudaGetSymbolAddress((void**)&wn, g_wnorm);
    __nv_bfloat16* xb; cudaGetSymbolAddress((void**)&xb, g_Xb);
    __nv_bfloat16* wb; cudaGetSymbolAddress((void**)&wb, g_Wb);

    cudaFuncSetAttribute(dist_topk_kernel,
                         cudaFuncAttributeMaxDynamicSharedMemorySize, SMEM_TOT);

    cvt_bf16_kernel<<<(NROWS * DIM / 8) / 256, 256>>>(X, xb, NROWS * DIM / 8);
    cvt_bf16_kernel<<<(KCODE * DIM / 8) / 256, 256>>>(W, wb, KCODE * DIM / 8);
    zero_counts_kernel<<<16, 256>>>();
    xla_norm_kernel<<<(NROWS * 4) / 256, 256>>>(X, xn, NROWS);
    xla_norm_kernel<<<(KCODE * 4) / 256, 256>>>(W, wn, KCODE);
    dist_topk_kernel<<<NROWS / RT, DTHREADS, SMEM_TOT>>>((unsigned long long*)enc_p, enc_p != nullptr);
    fused_assign_kernel<<<NROWS / 8, 256>>>(X, W, q_p, enc_p);
    finalize_kernel<<<1, 1024>>>(loss_p, perp_p);
}